// round 10
// baseline (speedup 1.0000x reference)
#include <cuda_runtime.h>
#include <cstdint>

#define NTOK 4096
#define DIM 768
#define NH 12
#define HD 64
#define RANK 4

// scratch (device globals: no allocation allowed)
__device__ float g_q[NH * NTOK * HD];
__device__ float g_k[NH * NTOK * HD];
__device__ float g_v[NH * NTOK * HD];
__device__ float g_tq[NTOK * RANK];
__device__ float g_tv[NTOK * RANK];
__device__ float g_bh[NH * NTOK * 64];
__device__ float g_bw[NH * NTOK * 64];
__device__ float g_o[NTOK * DIM];

__device__ __forceinline__ unsigned f2t(float x) {
    unsigned r;
    asm("cvt.rna.tf32.f32 %0, %1;" : "=r"(r) : "f"(x));
    return r;
}
__device__ __forceinline__ void mma8(float* c, unsigned a0, unsigned a1,
                                     unsigned a2, unsigned a3, unsigned b0,
                                     unsigned b1) {
    asm("mma.sync.aligned.m16n8k8.row.col.f32.tf32.tf32.f32 "
        "{%0,%1,%2,%3},{%4,%5,%6,%7},{%8,%9},{%0,%1,%2,%3};"
        : "+f"(c[0]), "+f"(c[1]), "+f"(c[2]), "+f"(c[3])
        : "r"(a0), "r"(a1), "r"(a2), "r"(a3), "r"(b0), "r"(b1));
}
__device__ __forceinline__ void cpa16(uint32_t dst, const float* src) {
    asm volatile("cp.async.cg.shared.global [%0], [%1], 16;" ::"r"(dst),
                 "l"(src));
}

// ---------------- kernel 1: t = x @ A^T (rank-4 LoRA down-proj) ----------------
__global__ void lora_t_kernel(const float* __restrict__ x,
                              const float* __restrict__ Aq,
                              const float* __restrict__ Av) {
    int warp = (blockIdx.x * blockDim.x + threadIdx.x) >> 5;
    int lane = threadIdx.x & 31;
    if (warp >= NTOK) return;
    const float* xr = x + warp * DIM;
    float p[8] = {0.f, 0.f, 0.f, 0.f, 0.f, 0.f, 0.f, 0.f};
    for (int i = lane; i < DIM; i += 32) {
        float xv = xr[i];
#pragma unroll
        for (int r = 0; r < RANK; r++) {
            p[r]        += xv * Aq[r * DIM + i];
            p[RANK + r] += xv * Av[r * DIM + i];
        }
    }
#pragma unroll
    for (int r = 0; r < 8; r++) {
#pragma unroll
        for (int o = 16; o; o >>= 1)
            p[r] += __shfl_xor_sync(0xffffffffu, p[r], o);
    }
    if (lane == 0) {
#pragma unroll
        for (int r = 0; r < RANK; r++) {
            g_tq[warp * RANK + r] = p[r];
            g_tv[warp * RANK + r] = p[RANK + r];
        }
    }
}

// ---------------- tf32 GEMM mainloop (shared by qkv/proj) ----------------
#define GST 36
#define GEMM_MAINLOOP(APTR, BPTR)                                              \
    __shared__ unsigned As[128 * GST];                                         \
    __shared__ unsigned Bs[128 * GST];                                         \
    int tid = threadIdx.x;                                                     \
    int warp = tid >> 5, lane = tid & 31;                                      \
    int g = lane >> 2, tig = lane & 3;                                         \
    int wm = warp & 1, wn = warp >> 1;                                         \
    int bm = blockIdx.y * 128, bn = blockIdx.x * 128;                          \
    int lrow = tid >> 1, lcol = (tid & 1) * 16;                                \
    float acc[4][4][4] = {};                                                   \
    for (int k0 = 0; k0 < DIM; k0 += 32) {                                     \
        _Pragma("unroll") for (int q = 0; q < 4; q++) {                        \
            float4 a4 = *(const float4*)&(APTR)[(bm + lrow) * DIM + k0 +       \
                                               lcol + q * 4];                  \
            unsigned* ad = &As[lrow * GST + lcol + q * 4];                     \
            ad[0] = f2t(a4.x); ad[1] = f2t(a4.y);                              \
            ad[2] = f2t(a4.z); ad[3] = f2t(a4.w);                              \
            float4 b4 = *(const float4*)&(BPTR)[(bn + lrow) * DIM + k0 +       \
                                               lcol + q * 4];                  \
            unsigned* bd = &Bs[lrow * GST + lcol + q * 4];                     \
            bd[0] = f2t(b4.x); bd[1] = f2t(b4.y);                              \
            bd[2] = f2t(b4.z); bd[3] = f2t(b4.w);                              \
        }                                                                      \
        __syncthreads();                                                       \
        _Pragma("unroll") for (int k8 = 0; k8 < 4; k8++) {                     \
            unsigned af[4][4], bf[4][2];                                       \
            _Pragma("unroll") for (int mt = 0; mt < 4; mt++) {                 \
                int r = (wm * 64 + mt * 16 + g) * GST + k8 * 8 + tig;          \
                af[mt][0] = As[r];            af[mt][1] = As[r + 8 * GST];     \
                af[mt][2] = As[r + 4];        af[mt][3] = As[r + 8 * GST + 4]; \
            }                                                                  \
            _Pragma("unroll") for (int nt = 0; nt < 4; nt++) {                 \
                int r = (wn * 32 + nt * 8 + g) * GST + k8 * 8 + tig;           \
                bf[nt][0] = Bs[r]; bf[nt][1] = Bs[r + 4];                      \
            }                                                                  \
            _Pragma("unroll") for (int mt = 0; mt < 4; mt++)                   \
                _Pragma("unroll") for (int nt = 0; nt < 4; nt++)               \
                    mma8(acc[mt][nt], af[mt][0], af[mt][1], af[mt][2],         \
                         af[mt][3], bf[nt][0], bf[nt][1]);                     \
        }                                                                      \
        __syncthreads();                                                       \
    }

// ---------------- kernel 2: qkv = x @ W_qkv^T + b + LoRA deltas ----------------
__global__ __launch_bounds__(256) void qkv_tc_kernel(
    const float* __restrict__ x, const float* __restrict__ W,
    const float* __restrict__ b, const float* __restrict__ Bq,
    const float* __restrict__ Bv) {
    GEMM_MAINLOOP(x, W)
    int which = bn / DIM;
    int hb = bn - which * DIM;
    float* dst = (which == 0) ? g_q : (which == 1 ? g_k : g_v);
#pragma unroll
    for (int mt = 0; mt < 4; mt++) {
#pragma unroll
        for (int h = 0; h < 2; h++) {
            int m = bm + wm * 64 + mt * 16 + g + 8 * h;
            float4 t4 = {0.f, 0.f, 0.f, 0.f};
            if (which == 0) t4 = *(const float4*)&g_tq[m * RANK];
            if (which == 2) t4 = *(const float4*)&g_tv[m * RANK];
#pragma unroll
            for (int nt = 0; nt < 4; nt++) {
                int cb = wn * 32 + nt * 8 + 2 * tig;
                int hcol = hb + cb;
                int head = hcol >> 6, c = hcol & 63;
                float v0 = acc[mt][nt][2 * h + 0] + b[bn + cb];
                float v1 = acc[mt][nt][2 * h + 1] + b[bn + cb + 1];
                if (which != 1) {
                    const float* Bp = ((which == 0) ? Bq : Bv) + hcol * RANK;
                    v0 += 0.25f * (t4.x * Bp[0] + t4.y * Bp[1] +
                                   t4.z * Bp[2] + t4.w * Bp[3]);
                    v1 += 0.25f * (t4.x * Bp[4] + t4.y * Bp[5] +
                                   t4.z * Bp[6] + t4.w * Bp[7]);
                }
                float2 o2 = {v0, v1};
                *(float2*)&dst[head * (NTOK * HD) + m * HD + c] = o2;
            }
        }
    }
}

// ---------------- kernel 5: out = O @ W_proj^T + b_proj ----------------
__global__ __launch_bounds__(256) void proj_tc_kernel(
    const float* __restrict__ W, const float* __restrict__ bp,
    float* __restrict__ out) {
    GEMM_MAINLOOP(g_o, W)
#pragma unroll
    for (int mt = 0; mt < 4; mt++) {
#pragma unroll
        for (int h = 0; h < 2; h++) {
            int m = bm + wm * 64 + mt * 16 + g + 8 * h;
#pragma unroll
            for (int nt = 0; nt < 4; nt++) {
                int n = bn + wn * 32 + nt * 8 + 2 * tig;
                float2 o2 = {acc[mt][nt][2 * h + 0] + bp[n],
                             acc[mt][nt][2 * h + 1] + bp[n + 1]};
                *(float2*)&out[m * DIM + n] = o2;
            }
        }
    }
}

// ---------------- kernel 3: decomposed rel-pos biases as 64x64x64 GEMM blocks --
__global__ __launch_bounds__(256) void bias2_kernel(
    const float* __restrict__ rel, int mode) {
    float* outg = mode ? g_bw : g_bh;
    __shared__ float Qs[64][68];
    __shared__ float Rs[64][68];
    int f = blockIdx.x;
    int head = blockIdx.y;
    int tid = threadIdx.x;
    int row = tid >> 2, cb = (tid & 3) * 16;
    int gi = (mode == 0) ? (f * 64 + row) : (row * 64 + f);
    const float* qp = &g_q[head * (NTOK * HD) + gi * HD + cb];
    const float* rp = &rel[(f + 63 - row) * HD + cb];
#pragma unroll
    for (int q4 = 0; q4 < 4; q4++) {
        float4 qv = *(const float4*)&qp[q4 * 4];
        float4 rv = *(const float4*)&rp[q4 * 4];
        int c = cb + q4 * 4;
        Qs[c + 0][row] = qv.x; Qs[c + 1][row] = qv.y;
        Qs[c + 2][row] = qv.z; Qs[c + 3][row] = qv.w;
        Rs[c + 0][row] = rv.x; Rs[c + 1][row] = rv.y;
        Rs[c + 2][row] = rv.z; Rs[c + 3][row] = rv.w;
    }
    __syncthreads();
    int tx = tid & 15, ty = tid >> 4;
    float s[4][4] = {};
#pragma unroll
    for (int c = 0; c < 64; c++) {
        float4 a4 = *(const float4*)&Qs[c][ty * 4];
        float4 b4 = *(const float4*)&Rs[c][tx * 4];
        float a[4] = {a4.x, a4.y, a4.z, a4.w};
        float bb[4] = {b4.x, b4.y, b4.z, b4.w};
#pragma unroll
        for (int i = 0; i < 4; i++)
#pragma unroll
            for (int j = 0; j < 4; j++) s[i][j] += a[i] * bb[j];
    }
#pragma unroll
    for (int i = 0; i < 4; i++) {
        int t = ty * 4 + i;
        int ig = (mode == 0) ? (f * 64 + t) : (t * 64 + f);
        float4 o4 = {s[i][0], s[i][1], s[i][2], s[i][3]};
        *(float4*)&outg[head * (NTOK * 64) + ig * 64 + tx * 4] = o4;
    }
}

// ---------------- kernel 4: flash attention, tf32 + cp.async double buffer ----
// K/V hold RAW fp32 bits (HMMA.TF32 reads only the tf32 bit-field; softmax
// shift-invariance absorbs the K truncation bias, V bias ~3e-4 acceptable).
// P stored with RNA conversion (f2t) to avoid numerator-only truncation bias.
// 2-stage cp.async pipeline: tile kt+1 streams in while tile kt computes.
#define KS_ST 68
#define VS_ST 72
#define PS_ST 68
#define STAGE_W (64 * KS_ST + 64 * VS_ST)  // words per stage (8960)
__global__ __launch_bounds__(128) void attn_kernel() {
    extern __shared__ unsigned smu[];
    unsigned* Ps = smu + 2 * STAGE_W;  // [64][68]

    int head = blockIdx.y;
    int q0 = blockIdx.x * 64;
    int tid = threadIdx.x;
    int warp = tid >> 5, lane = tid & 31;
    int g = lane >> 2, tig = lane & 3;
    int r0 = warp * 16 + g, r1 = r0 + 8;

    const float* qg = g_q + head * (NTOK * HD) + q0 * HD;
    const float* kg = g_k + head * (NTOK * HD);
    const float* vg = g_v + head * (NTOK * HD);
    const float* bhg = g_bh + head * (NTOK * 64);
    const float* bwg = g_bw + head * (NTOK * 64);

    uint32_t sbase = (uint32_t)__cvta_generic_to_shared(smu);

    unsigned qf[8][4];
#pragma unroll
    for (int kk = 0; kk < 8; kk++) {
        qf[kk][0] = f2t(qg[r0 * 64 + kk * 8 + tig] * 0.125f);
        qf[kk][1] = f2t(qg[r1 * 64 + kk * 8 + tig] * 0.125f);
        qf[kk][2] = f2t(qg[r0 * 64 + kk * 8 + tig + 4] * 0.125f);
        qf[kk][3] = f2t(qg[r1 * 64 + kk * 8 + tig + 4] * 0.125f);
    }
    float bw0[16], bw1[16];
#pragma unroll
    for (int jj = 0; jj < 8; jj++) {
        float2 t0 = *(const float2*)&bwg[(q0 + r0) * 64 + jj * 8 + 2 * tig];
        float2 t1 = *(const float2*)&bwg[(q0 + r1) * 64 + jj * 8 + 2 * tig];
        bw0[2 * jj] = t0.x; bw0[2 * jj + 1] = t0.y;
        bw1[2 * jj] = t1.x; bw1[2 * jj + 1] = t1.y;
    }

    float oac[8][4] = {};
    float m0 = -1e30f, m1 = -1e30f, l0 = 0.f, l1 = 0.f;

    // issue tile 0 into stage 0: 1024 16B-chunks each for K and V
    {
        uint32_t kd = sbase;
        uint32_t vd = sbase + 64 * KS_ST * 4;
#pragma unroll
        for (int c = 0; c < 1024; c += 128) {
            int cc = c + tid;
            int row = cc >> 4, col = (cc & 15) * 4;
            cpa16(kd + (row * KS_ST + col) * 4, kg + row * 64 + col);
            cpa16(vd + (row * VS_ST + col) * 4, vg + row * 64 + col);
        }
        asm volatile("cp.async.commit_group;");
    }

    for (int kt = 0; kt < 64; kt++) {
        int cur = kt & 1;
        unsigned* Ks = smu + cur * STAGE_W;
        unsigned* Vs = Ks + 64 * KS_ST;

        __syncthreads();  // all threads done computing on stage cur^1
        if (kt + 1 < 64) {
            const float* kn = kg + (kt + 1) * 64 * 64;
            const float* vn = vg + (kt + 1) * 64 * 64;
            uint32_t kd = sbase + (cur ^ 1) * STAGE_W * 4;
            uint32_t vd = kd + 64 * KS_ST * 4;
#pragma unroll
            for (int c = 0; c < 1024; c += 128) {
                int cc = c + tid;
                int row = cc >> 4, col = (cc & 15) * 4;
                cpa16(kd + (row * KS_ST + col) * 4, kn + row * 64 + col);
                cpa16(vd + (row * VS_ST + col) * 4, vn + row * 64 + col);
            }
            asm volatile("cp.async.commit_group;");
            asm volatile("cp.async.wait_group 1;");  // tile kt complete
        } else {
            asm volatile("cp.async.wait_group 0;");
        }
        __syncthreads();

        // S = (Q/8) . K^T
        float sac[8][4] = {};
#pragma unroll
        for (int kk = 0; kk < 8; kk++) {
#pragma unroll
            for (int jj = 0; jj < 8; jj++) {
                unsigned b0 = Ks[(jj * 8 + g) * KS_ST + kk * 8 + tig];
                unsigned b1 = Ks[(jj * 8 + g) * KS_ST + kk * 8 + tig + 4];
                mma8(sac[jj], qf[kk][0], qf[kk][1], qf[kk][2], qf[kk][3], b0, b1);
            }
        }

        float bh0 = __ldg(&bhg[(q0 + r0) * 64 + kt]);
        float bh1 = __ldg(&bhg[(q0 + r1) * 64 + kt]);
        float mt0 = -1e30f, mt1 = -1e30f;
#pragma unroll
        for (int jj = 0; jj < 8; jj++) {
            sac[jj][0] += bh0 + bw0[2 * jj];
            sac[jj][1] += bh0 + bw0[2 * jj + 1];
            sac[jj][2] += bh1 + bw1[2 * jj];
            sac[jj][3] += bh1 + bw1[2 * jj + 1];
            mt0 = fmaxf(mt0, fmaxf(sac[jj][0], sac[jj][1]));
            mt1 = fmaxf(mt1, fmaxf(sac[jj][2], sac[jj][3]));
        }
#pragma unroll
        for (int o = 1; o < 4; o <<= 1) {
            mt0 = fmaxf(mt0, __shfl_xor_sync(0xffffffffu, mt0, o));
            mt1 = fmaxf(mt1, __shfl_xor_sync(0xffffffffu, mt1, o));
        }
        float mn0 = fmaxf(m0, mt0), mn1 = fmaxf(m1, mt1);
        float c0 = __expf(m0 - mn0), c1 = __expf(m1 - mn1);
        float s0 = 0.f, s1 = 0.f;
#pragma unroll
        for (int jj = 0; jj < 8; jj++) {
            sac[jj][0] = __expf(sac[jj][0] - mn0);
            sac[jj][1] = __expf(sac[jj][1] - mn0);
            sac[jj][2] = __expf(sac[jj][2] - mn1);
            sac[jj][3] = __expf(sac[jj][3] - mn1);
            s0 += sac[jj][0] + sac[jj][1];
            s1 += sac[jj][2] + sac[jj][3];
        }
#pragma unroll
        for (int o = 1; o < 4; o <<= 1) {
            s0 += __shfl_xor_sync(0xffffffffu, s0, o);
            s1 += __shfl_xor_sync(0xffffffffu, s1, o);
        }
        l0 = l0 * c0 + s0; l1 = l1 * c1 + s1;
        m0 = mn0; m1 = mn1;
#pragma unroll
        for (int jj = 0; jj < 8; jj++) {
            oac[jj][0] *= c0; oac[jj][1] *= c0;
            oac[jj][2] *= c1; oac[jj][3] *= c1;
        }

        // store P (RNA tf32) — each warp touches only its own 16 rows
#pragma unroll
        for (int jj = 0; jj < 8; jj++) {
            Ps[r0 * PS_ST + jj * 8 + 2 * tig]     = f2t(sac[jj][0]);
            Ps[r0 * PS_ST + jj * 8 + 2 * tig + 1] = f2t(sac[jj][1]);
            Ps[r1 * PS_ST + jj * 8 + 2 * tig]     = f2t(sac[jj][2]);
            Ps[r1 * PS_ST + jj * 8 + 2 * tig + 1] = f2t(sac[jj][3]);
        }
        __syncwarp();  // warp-local: A-frags below read only this warp's rows

        // O += P @ V
#pragma unroll
        for (int kk = 0; kk < 8; kk++) {
            unsigned a0 = Ps[r0 * PS_ST + kk * 8 + tig];
            unsigned a1 = Ps[r1 * PS_ST + kk * 8 + tig];
            unsigned a2 = Ps[r0 * PS_ST + kk * 8 + tig + 4];
            unsigned a3 = Ps[r1 * PS_ST + kk * 8 + tig + 4];
#pragma unroll
            for (int jj = 0; jj < 8; jj++) {
                unsigned b0 = Vs[(kk * 8 + tig) * VS_ST + jj * 8 + g];
                unsigned b1 = Vs[(kk * 8 + tig + 4) * VS_ST + jj * 8 + g];
                mma8(oac[jj], a0, a1, a2, a3, b0, b1);
            }
        }
    }

    float inv0 = 1.f / l0, inv1 = 1.f / l1;
#pragma unroll
    for (int jj = 0; jj < 8; jj++) {
        int c = head * 64 + jj * 8 + 2 * tig;
        float2 o0 = {oac[jj][0] * inv0, oac[jj][1] * inv0};
        float2 o1 = {oac[jj][2] * inv1, oac[jj][3] * inv1};
        *(float2*)&g_o[(q0 + r0) * DIM + c] = o0;
        *(float2*)&g_o[(q0 + r1) * DIM + c] = o1;
    }
}

extern "C" void kernel_launch(void* const* d_in, const int* in_sizes, int n_in,
                              void* d_out, int out_size) {
    const float* x      = (const float*)d_in[0];
    const float* W_qkv  = (const float*)d_in[1];
    const float* b_qkv  = (const float*)d_in[2];
    const float* A_q    = (const float*)d_in[3];
    const float* B_q    = (const float*)d_in[4];
    const float* A_v    = (const float*)d_in[5];
    const float* B_v    = (const float*)d_in[6];
    const float* rel_h  = (const float*)d_in[7];
    const float* rel_w  = (const float*)d_in[8];
    const float* W_proj = (const float*)d_in[9];
    const float* b_proj = (const float*)d_in[10];
    float* out = (float*)d_out;

    static int smem_set = 0;
    int attn_smem = (2 * STAGE_W + 64 * PS_ST) * 4;  // 89088 B
    if (!smem_set) {
        cudaFuncSetAttribute(attn_kernel,
                             cudaFuncAttributeMaxDynamicSharedMemorySize,
                             attn_smem);
        smem_set = 1;
    }

    lora_t_kernel<<<512, 256>>>(x, A_q, A_v);
    qkv_tc_kernel<<<dim3(18, 32), 256>>>(x, W_qkv, b_qkv, B_q, B_v);
    bias2_kernel<<<dim3(64, 12), 256>>>(rel_h, 0);
    bias2_kernel<<<dim3(64, 12), 256>>>(rel_w, 1);
    attn_kernel<<<dim3(64, 12), 128, attn_smem>>>();
    proj_tc_kernel<<<dim3(6, 32), 256>>>(W_proj, b_proj, out);
}

// round 13
// speedup vs baseline: 1.0226x; 1.0226x over previous
#include <cuda_runtime.h>
#include <cstdint>

#define NTOK 4096
#define DIM 768
#define NH 12
#define HD 64
#define RANK 4

// scratch (device globals: no allocation allowed)
__device__ float g_q[NH * NTOK * HD];
__device__ float g_k[NH * NTOK * HD];
__device__ float g_v[NH * NTOK * HD];
__device__ float g_tq[NTOK * RANK];
__device__ float g_tv[NTOK * RANK];
__device__ float g_bh[NH * NTOK * 64];
__device__ float g_bw[NH * NTOK * 64];
__device__ float g_o[NTOK * DIM];

__device__ __forceinline__ unsigned f2t(float x) {
    unsigned r;
    asm("cvt.rna.tf32.f32 %0, %1;" : "=r"(r) : "f"(x));
    return r;
}
__device__ __forceinline__ void mma8(float* c, unsigned a0, unsigned a1,
                                     unsigned a2, unsigned a3, unsigned b0,
                                     unsigned b1) {
    asm("mma.sync.aligned.m16n8k8.row.col.f32.tf32.tf32.f32 "
        "{%0,%1,%2,%3},{%4,%5,%6,%7},{%8,%9},{%0,%1,%2,%3};"
        : "+f"(c[0]), "+f"(c[1]), "+f"(c[2]), "+f"(c[3])
        : "r"(a0), "r"(a1), "r"(a2), "r"(a3), "r"(b0), "r"(b1));
}

// ---------------- kernel 1: t = x @ A^T (rank-4 LoRA down-proj) ----------------
__global__ void lora_t_kernel(const float* __restrict__ x,
                              const float* __restrict__ Aq,
                              const float* __restrict__ Av) {
    int warp = (blockIdx.x * blockDim.x + threadIdx.x) >> 5;
    int lane = threadIdx.x & 31;
    if (warp >= NTOK) return;
    const float* xr = x + warp * DIM;
    float p[8] = {0.f, 0.f, 0.f, 0.f, 0.f, 0.f, 0.f, 0.f};
    for (int i = lane; i < DIM; i += 32) {
        float xv = xr[i];
#pragma unroll
        for (int r = 0; r < RANK; r++) {
            p[r]        += xv * Aq[r * DIM + i];
            p[RANK + r] += xv * Av[r * DIM + i];
        }
    }
#pragma unroll
    for (int r = 0; r < 8; r++) {
#pragma unroll
        for (int o = 16; o; o >>= 1)
            p[r] += __shfl_xor_sync(0xffffffffu, p[r], o);
    }
    if (lane == 0) {
#pragma unroll
        for (int r = 0; r < RANK; r++) {
            g_tq[warp * RANK + r] = p[r];
            g_tv[warp * RANK + r] = p[RANK + r];
        }
    }
}

// ---------------- tf32 GEMM mainloop (shared by qkv/proj) ----------------
#define GST 36
#define GEMM_MAINLOOP(APTR, BPTR)                                              \
    __shared__ unsigned As[128 * GST];                                         \
    __shared__ unsigned Bs[128 * GST];                                         \
    int tid = threadIdx.x;                                                     \
    int warp = tid >> 5, lane = tid & 31;                                      \
    int g = lane >> 2, tig = lane & 3;                                         \
    int wm = warp & 1, wn = warp >> 1;                                         \
    int bm = blockIdx.y * 128, bn = blockIdx.x * 128;                          \
    int lrow = tid >> 1, lcol = (tid & 1) * 16;                                \
    float acc[4][4][4] = {};                                                   \
    for (int k0 = 0; k0 < DIM; k0 += 32) {                                     \
        _Pragma("unroll") for (int q = 0; q < 4; q++) {                        \
            float4 a4 = *(const float4*)&(APTR)[(bm + lrow) * DIM + k0 +       \
                                               lcol + q * 4];                  \
            unsigned* ad = &As[lrow * GST + lcol + q * 4];                     \
            ad[0] = f2t(a4.x); ad[1] = f2t(a4.y);                              \
            ad[2] = f2t(a4.z); ad[3] = f2t(a4.w);                              \
            float4 b4 = *(const float4*)&(BPTR)[(bn + lrow) * DIM + k0 +       \
                                               lcol + q * 4];                  \
            unsigned* bd = &Bs[lrow * GST + lcol + q * 4];                     \
            bd[0] = f2t(b4.x); bd[1] = f2t(b4.y);                              \
            bd[2] = f2t(b4.z); bd[3] = f2t(b4.w);                              \
        }                                                                      \
        __syncthreads();                                                       \
        _Pragma("unroll") for (int k8 = 0; k8 < 4; k8++) {                     \
            unsigned af[4][4], bf[4][2];                                       \
            _Pragma("unroll") for (int mt = 0; mt < 4; mt++) {                 \
                int r = (wm * 64 + mt * 16 + g) * GST + k8 * 8 + tig;          \
                af[mt][0] = As[r];            af[mt][1] = As[r + 8 * GST];     \
                af[mt][2] = As[r + 4];        af[mt][3] = As[r + 8 * GST + 4]; \
            }                                                                  \
            _Pragma("unroll") for (int nt = 0; nt < 4; nt++) {                 \
                int r = (wn * 32 + nt * 8 + g) * GST + k8 * 8 + tig;           \
                bf[nt][0] = Bs[r]; bf[nt][1] = Bs[r + 4];                      \
            }                                                                  \
            _Pragma("unroll") for (int mt = 0; mt < 4; mt++)                   \
                _Pragma("unroll") for (int nt = 0; nt < 4; nt++)               \
                    mma8(acc[mt][nt], af[mt][0], af[mt][1], af[mt][2],         \
                         af[mt][3], bf[nt][0], bf[nt][1]);                     \
        }                                                                      \
        __syncthreads();                                                       \
    }

// ---------------- kernel 2: qkv = x @ W_qkv^T + b + LoRA deltas ----------------
__global__ __launch_bounds__(256) void qkv_tc_kernel(
    const float* __restrict__ x, const float* __restrict__ W,
    const float* __restrict__ b, const float* __restrict__ Bq,
    const float* __restrict__ Bv) {
    GEMM_MAINLOOP(x, W)
    int which = bn / DIM;
    int hb = bn - which * DIM;
    float* dst = (which == 0) ? g_q : (which == 1 ? g_k : g_v);
#pragma unroll
    for (int mt = 0; mt < 4; mt++) {
#pragma unroll
        for (int h = 0; h < 2; h++) {
            int m = bm + wm * 64 + mt * 16 + g + 8 * h;
            float4 t4 = {0.f, 0.f, 0.f, 0.f};
            if (which == 0) t4 = *(const float4*)&g_tq[m * RANK];
            if (which == 2) t4 = *(const float4*)&g_tv[m * RANK];
#pragma unroll
            for (int nt = 0; nt < 4; nt++) {
                int cb = wn * 32 + nt * 8 + 2 * tig;
                int hcol = hb + cb;
                int head = hcol >> 6, c = hcol & 63;
                float v0 = acc[mt][nt][2 * h + 0] + b[bn + cb];
                float v1 = acc[mt][nt][2 * h + 1] + b[bn + cb + 1];
                if (which != 1) {
                    const float* Bp = ((which == 0) ? Bq : Bv) + hcol * RANK;
                    v0 += 0.25f * (t4.x * Bp[0] + t4.y * Bp[1] +
                                   t4.z * Bp[2] + t4.w * Bp[3]);
                    v1 += 0.25f * (t4.x * Bp[4] + t4.y * Bp[5] +
                                   t4.z * Bp[6] + t4.w * Bp[7]);
                }
                float2 o2 = {v0, v1};
                *(float2*)&dst[head * (NTOK * HD) + m * HD + c] = o2;
            }
        }
    }
}

// ---------------- kernel 5: out = O @ W_proj^T + b_proj ----------------
__global__ __launch_bounds__(256) void proj_tc_kernel(
    const float* __restrict__ W, const float* __restrict__ bp,
    float* __restrict__ out) {
    GEMM_MAINLOOP(g_o, W)
#pragma unroll
    for (int mt = 0; mt < 4; mt++) {
#pragma unroll
        for (int h = 0; h < 2; h++) {
            int m = bm + wm * 64 + mt * 16 + g + 8 * h;
#pragma unroll
            for (int nt = 0; nt < 4; nt++) {
                int n = bn + wn * 32 + nt * 8 + 2 * tig;
                float2 o2 = {acc[mt][nt][2 * h + 0] + bp[n],
                             acc[mt][nt][2 * h + 1] + bp[n + 1]};
                *(float2*)&out[m * DIM + n] = o2;
            }
        }
    }
}

// ---------------- kernel 3: decomposed rel-pos biases as 64x64x64 GEMM blocks --
__global__ __launch_bounds__(256) void bias2_kernel(
    const float* __restrict__ rel, int mode) {
    float* outg = mode ? g_bw : g_bh;
    __shared__ float Qs[64][68];
    __shared__ float Rs[64][68];
    int f = blockIdx.x;
    int head = blockIdx.y;
    int tid = threadIdx.x;
    int row = tid >> 2, cb = (tid & 3) * 16;
    int gi = (mode == 0) ? (f * 64 + row) : (row * 64 + f);
    const float* qp = &g_q[head * (NTOK * HD) + gi * HD + cb];
    const float* rp = &rel[(f + 63 - row) * HD + cb];
#pragma unroll
    for (int q4 = 0; q4 < 4; q4++) {
        float4 qv = *(const float4*)&qp[q4 * 4];
        float4 rv = *(const float4*)&rp[q4 * 4];
        int c = cb + q4 * 4;
        Qs[c + 0][row] = qv.x; Qs[c + 1][row] = qv.y;
        Qs[c + 2][row] = qv.z; Qs[c + 3][row] = qv.w;
        Rs[c + 0][row] = rv.x; Rs[c + 1][row] = rv.y;
        Rs[c + 2][row] = rv.z; Rs[c + 3][row] = rv.w;
    }
    __syncthreads();
    int tx = tid & 15, ty = tid >> 4;
    float s[4][4] = {};
#pragma unroll
    for (int c = 0; c < 64; c++) {
        float4 a4 = *(const float4*)&Qs[c][ty * 4];
        float4 b4 = *(const float4*)&Rs[c][tx * 4];
        float a[4] = {a4.x, a4.y, a4.z, a4.w};
        float bb[4] = {b4.x, b4.y, b4.z, b4.w};
#pragma unroll
        for (int i = 0; i < 4; i++)
#pragma unroll
            for (int j = 0; j < 4; j++) s[i][j] += a[i] * bb[j];
    }
#pragma unroll
    for (int i = 0; i < 4; i++) {
        int t = ty * 4 + i;
        int ig = (mode == 0) ? (f * 64 + t) : (t * 64 + f);
        float4 o4 = {s[i][0], s[i][1], s[i][2], s[i][3]};
        *(float4*)&outg[head * (NTOK * 64) + ig * 64 + tx * 4] = o4;
    }
}

// ---------------- kernel 4: flash attention, tf32, BM=128 ----------------
// 256 threads (8 warps), q-tile = 128 rows, key tile = 64 keys (one h2 row).
// K/V smem holds RAW fp32 bits (HMMA.TF32 reads only the tf32 field; validated
// R10 at rel_err 2.9e-4). Q pre-scaled + RNA; P stored with RNA f2t.
// K/V tile amortized over 2x q rows vs the 64-row version; same warps/SM.
#define KS_ST 68
#define VS_ST 72
#define PS_ST 68
__global__ __launch_bounds__(256) void attn_kernel() {
    extern __shared__ unsigned smu[];
    unsigned* Ks = smu;                            // [64][68] raw fp32 bits
    unsigned* Vs = smu + 64 * KS_ST;               // [64][72]
    unsigned* Ps = smu + 64 * KS_ST + 64 * VS_ST;  // [128][68]

    int head = blockIdx.y;
    int q0 = blockIdx.x * 128;
    int tid = threadIdx.x;
    int warp = tid >> 5, lane = tid & 31;
    int g = lane >> 2, tig = lane & 3;
    int r0 = warp * 16 + g, r1 = r0 + 8;  // local q rows (0..127)

    const float* qg = g_q + head * (NTOK * HD) + q0 * HD;
    const float* kg = g_k + head * (NTOK * HD);
    const float* vg = g_v + head * (NTOK * HD);
    const float* bhg = g_bh + head * (NTOK * 64);
    const float* bwg = g_bw + head * (NTOK * 64);

    // Q fragments, pre-scaled by 1/8 (exact), RNA tf32
    unsigned qf[8][4];
#pragma unroll
    for (int kk = 0; kk < 8; kk++) {
        qf[kk][0] = f2t(qg[r0 * 64 + kk * 8 + tig] * 0.125f);
        qf[kk][1] = f2t(qg[r1 * 64 + kk * 8 + tig] * 0.125f);
        qf[kk][2] = f2t(qg[r0 * 64 + kk * 8 + tig + 4] * 0.125f);
        qf[kk][3] = f2t(qg[r1 * 64 + kk * 8 + tig + 4] * 0.125f);
    }
    // bias_w: loop-invariant over key tiles
    float bw0[16], bw1[16];
#pragma unroll
    for (int jj = 0; jj < 8; jj++) {
        float2 t0 = *(const float2*)&bwg[(q0 + r0) * 64 + jj * 8 + 2 * tig];
        float2 t1 = *(const float2*)&bwg[(q0 + r1) * 64 + jj * 8 + 2 * tig];
        bw0[2 * jj] = t0.x; bw0[2 * jj + 1] = t0.y;
        bw1[2 * jj] = t1.x; bw1[2 * jj + 1] = t1.y;
    }

    float oac[8][4] = {};
    float m0 = -1e30f, m1 = -1e30f, l0 = 0.f, l1 = 0.f;

    for (int kt = 0; kt < 64; kt++) {
        __syncthreads();  // prior K/V reads complete before overwrite
        // raw-bit copy gmem -> smem (4 K chunks + 4 V chunks per thread)
#pragma unroll
        for (int l = 0; l < 1024; l += 256) {
            int cc = l + tid;
            int j = cc >> 4, cb = (cc & 15) * 4;
            uint4 k4 = *(const uint4*)&kg[(kt * 64 + j) * 64 + cb];
            *(uint4*)&Ks[j * KS_ST + cb] = k4;
            uint4 v4 = *(const uint4*)&vg[(kt * 64 + j) * 64 + cb];
            *(uint4*)&Vs[j * VS_ST + cb] = v4;
        }
        __syncthreads();

        // S = (Q/8) . K^T
        float sac[8][4] = {};
#pragma unroll
        for (int kk = 0; kk < 8; kk++) {
#pragma unroll
            for (int jj = 0; jj < 8; jj++) {
                unsigned b0 = Ks[(jj * 8 + g) * KS_ST + kk * 8 + tig];
                unsigned b1 = Ks[(jj * 8 + g) * KS_ST + kk * 8 + tig + 4];
                mma8(sac[jj], qf[kk][0], qf[kk][1], qf[kk][2], qf[kk][3], b0, b1);
            }
        }

        // biases + online softmax
        float bh0 = __ldg(&bhg[(q0 + r0) * 64 + kt]);
        float bh1 = __ldg(&bhg[(q0 + r1) * 64 + kt]);
        float mt0 = -1e30f, mt1 = -1e30f;
#pragma unroll
        for (int jj = 0; jj < 8; jj++) {
            sac[jj][0] += bh0 + bw0[2 * jj];
            sac[jj][1] += bh0 + bw0[2 * jj + 1];
            sac[jj][2] += bh1 + bw1[2 * jj];
            sac[jj][3] += bh1 + bw1[2 * jj + 1];
            mt0 = fmaxf(mt0, fmaxf(sac[jj][0], sac[jj][1]));
            mt1 = fmaxf(mt1, fmaxf(sac[jj][2], sac[jj][3]));
        }
#pragma unroll
        for (int o = 1; o < 4; o <<= 1) {
            mt0 = fmaxf(mt0, __shfl_xor_sync(0xffffffffu, mt0, o));
            mt1 = fmaxf(mt1, __shfl_xor_sync(0xffffffffu, mt1, o));
        }
        float mn0 = fmaxf(m0, mt0), mn1 = fmaxf(m1, mt1);
        float c0 = __expf(m0 - mn0), c1 = __expf(m1 - mn1);
        float s0 = 0.f, s1 = 0.f;
#pragma unroll
        for (int jj = 0; jj < 8; jj++) {
            sac[jj][0] = __expf(sac[jj][0] - mn0);
            sac[jj][1] = __expf(sac[jj][1] - mn0);
            sac[jj][2] = __expf(sac[jj][2] - mn1);
            sac[jj][3] = __expf(sac[jj][3] - mn1);
            s0 += sac[jj][0] + sac[jj][1];
            s1 += sac[jj][2] + sac[jj][3];
        }
#pragma unroll
        for (int o = 1; o < 4; o <<= 1) {
            s0 += __shfl_xor_sync(0xffffffffu, s0, o);
            s1 += __shfl_xor_sync(0xffffffffu, s1, o);
        }
        l0 = l0 * c0 + s0; l1 = l1 * c1 + s1;
        m0 = mn0; m1 = mn1;
#pragma unroll
        for (int jj = 0; jj < 8; jj++) {
            oac[jj][0] *= c0; oac[jj][1] *= c0;
            oac[jj][2] *= c1; oac[jj][3] *= c1;
        }

        // store P (RNA tf32) — each warp touches only its own 16 rows
#pragma unroll
        for (int jj = 0; jj < 8; jj++) {
            Ps[r0 * PS_ST + jj * 8 + 2 * tig]     = f2t(sac[jj][0]);
            Ps[r0 * PS_ST + jj * 8 + 2 * tig + 1] = f2t(sac[jj][1]);
            Ps[r1 * PS_ST + jj * 8 + 2 * tig]     = f2t(sac[jj][2]);
            Ps[r1 * PS_ST + jj * 8 + 2 * tig + 1] = f2t(sac[jj][3]);
        }
        __syncwarp();  // warp-local: A-frags below read only this warp's rows

        // O += P @ V
#pragma unroll
        for (int kk = 0; kk < 8; kk++) {
            unsigned a0 = Ps[r0 * PS_ST + kk * 8 + tig];
            unsigned a1 = Ps[r1 * PS_ST + kk * 8 + tig];
            unsigned a2 = Ps[r0 * PS_ST + kk * 8 + tig + 4];
            unsigned a3 = Ps[r1 * PS_ST + kk * 8 + tig + 4];
#pragma unroll
            for (int jj = 0; jj < 8; jj++) {
                unsigned b0 = Vs[(kk * 8 + tig) * VS_ST + jj * 8 + g];
                unsigned b1 = Vs[(kk * 8 + tig + 4) * VS_ST + jj * 8 + g];
                mma8(oac[jj], a0, a1, a2, a3, b0, b1);
            }
        }
    }

    float inv0 = 1.f / l0, inv1 = 1.f / l1;
#pragma unroll
    for (int jj = 0; jj < 8; jj++) {
        int c = head * 64 + jj * 8 + 2 * tig;
        float2 o0 = {oac[jj][0] * inv0, oac[jj][1] * inv0};
        float2 o1 = {oac[jj][2] * inv1, oac[jj][3] * inv1};
        *(float2*)&g_o[(q0 + r0) * DIM + c] = o0;
        *(float2*)&g_o[(q0 + r1) * DIM + c] = o1;
    }
}

extern "C" void kernel_launch(void* const* d_in, const int* in_sizes, int n_in,
                              void* d_out, int out_size) {
    const float* x      = (const float*)d_in[0];
    const float* W_qkv  = (const float*)d_in[1];
    const float* b_qkv  = (const float*)d_in[2];
    const float* A_q    = (const float*)d_in[3];
    const float* B_q    = (const float*)d_in[4];
    const float* A_v    = (const float*)d_in[5];
    const float* B_v    = (const float*)d_in[6];
    const float* rel_h  = (const float*)d_in[7];
    const float* rel_w  = (const float*)d_in[8];
    const float* W_proj = (const float*)d_in[9];
    const float* b_proj = (const float*)d_in[10];
    float* out = (float*)d_out;

    static int smem_set = 0;
    int attn_smem = (64 * KS_ST + 64 * VS_ST + 128 * PS_ST) * 4;  // 70656 B
    if (!smem_set) {
        cudaFuncSetAttribute(attn_kernel,
                             cudaFuncAttributeMaxDynamicSharedMemorySize,
                             attn_smem);
        smem_set = 1;
    }

    lora_t_kernel<<<512, 256>>>(x, A_q, A_v);
    qkv_tc_kernel<<<dim3(18, 32), 256>>>(x, W_qkv, b_qkv, B_q, B_v);
    bias2_kernel<<<dim3(64, 12), 256>>>(rel_h, 0);
    bias2_kernel<<<dim3(64, 12), 256>>>(rel_w, 1);
    attn_kernel<<<dim3(32, 12), 256, attn_smem>>>();
    proj_tc_kernel<<<dim3(6, 32), 256>>>(W_proj, b_proj, out);
}

// round 15
// speedup vs baseline: 1.5556x; 1.5213x over previous
#include <cuda_runtime.h>
#include <cuda_fp16.h>
#include <cstdint>

#define NTOK 4096
#define DIM 768
#define NH 12
#define HD 64
#define RANK 4

// scratch (device globals: no allocation allowed)
__device__ float g_q[NH * NTOK * HD];          // fp32 q (bias kernels)
__device__ __half g_qh[NH * NTOK * HD];        // fp16 q, pre-scaled by 1/8
__device__ __half g_kh[NH * NTOK * HD];        // fp16 k, [head][token][hd]
__device__ __half g_vh[NH * HD * NTOK];        // fp16 v, TRANSPOSED [head][hd][token]
__device__ float g_tq[NTOK * RANK];
__device__ float g_tv[NTOK * RANK];
__device__ float g_bh[NH * NTOK * 64];
__device__ float g_bw[NH * NTOK * 64];
__device__ float g_o[NTOK * DIM];

__device__ __forceinline__ unsigned f2t(float x) {
    unsigned r;
    asm("cvt.rna.tf32.f32 %0, %1;" : "=r"(r) : "f"(x));
    return r;
}
__device__ __forceinline__ unsigned packh2(float lo, float hi) {
    unsigned r;
    asm("cvt.rn.f16x2.f32 %0, %1, %2;" : "=r"(r) : "f"(hi), "f"(lo));
    return r;
}
__device__ __forceinline__ void mma8(float* c, unsigned a0, unsigned a1,
                                     unsigned a2, unsigned a3, unsigned b0,
                                     unsigned b1) {
    asm("mma.sync.aligned.m16n8k8.row.col.f32.tf32.tf32.f32 "
        "{%0,%1,%2,%3},{%4,%5,%6,%7},{%8,%9},{%0,%1,%2,%3};"
        : "+f"(c[0]), "+f"(c[1]), "+f"(c[2]), "+f"(c[3])
        : "r"(a0), "r"(a1), "r"(a2), "r"(a3), "r"(b0), "r"(b1));
}
__device__ __forceinline__ void mma16(float* c, unsigned a0, unsigned a1,
                                      unsigned a2, unsigned a3, unsigned b0,
                                      unsigned b1) {
    asm("mma.sync.aligned.m16n8k16.row.col.f32.f16.f16.f32 "
        "{%0,%1,%2,%3},{%4,%5,%6,%7},{%8,%9},{%0,%1,%2,%3};"
        : "+f"(c[0]), "+f"(c[1]), "+f"(c[2]), "+f"(c[3])
        : "r"(a0), "r"(a1), "r"(a2), "r"(a3), "r"(b0), "r"(b1));
}

// ---------------- kernel 1: t = x @ A^T (rank-4 LoRA down-proj) ----------------
__global__ void lora_t_kernel(const float* __restrict__ x,
                              const float* __restrict__ Aq,
                              const float* __restrict__ Av) {
    int warp = (blockIdx.x * blockDim.x + threadIdx.x) >> 5;
    int lane = threadIdx.x & 31;
    if (warp >= NTOK) return;
    const float* xr = x + warp * DIM;
    float p[8] = {0.f, 0.f, 0.f, 0.f, 0.f, 0.f, 0.f, 0.f};
    for (int i = lane; i < DIM; i += 32) {
        float xv = xr[i];
#pragma unroll
        for (int r = 0; r < RANK; r++) {
            p[r]        += xv * Aq[r * DIM + i];
            p[RANK + r] += xv * Av[r * DIM + i];
        }
    }
#pragma unroll
    for (int r = 0; r < 8; r++) {
#pragma unroll
        for (int o = 16; o; o >>= 1)
            p[r] += __shfl_xor_sync(0xffffffffu, p[r], o);
    }
    if (lane == 0) {
#pragma unroll
        for (int r = 0; r < RANK; r++) {
            g_tq[warp * RANK + r] = p[r];
            g_tv[warp * RANK + r] = p[RANK + r];
        }
    }
}

// ---------------- tf32 GEMM mainloop (shared by qkv/proj) ----------------
#define GST 36
#define GEMM_MAINLOOP(APTR, BPTR)                                              \
    __shared__ unsigned As[128 * GST];                                         \
    __shared__ unsigned Bs[128 * GST];                                         \
    int tid = threadIdx.x;                                                     \
    int warp = tid >> 5, lane = tid & 31;                                      \
    int g = lane >> 2, tig = lane & 3;                                         \
    int wm = warp & 1, wn = warp >> 1;                                         \
    int bm = blockIdx.y * 128, bn = blockIdx.x * 128;                          \
    int lrow = tid >> 1, lcol = (tid & 1) * 16;                                \
    float acc[4][4][4] = {};                                                   \
    for (int k0 = 0; k0 < DIM; k0 += 32) {                                     \
        _Pragma("unroll") for (int q = 0; q < 4; q++) {                        \
            float4 a4 = *(const float4*)&(APTR)[(bm + lrow) * DIM + k0 +       \
                                               lcol + q * 4];                  \
            unsigned* ad = &As[lrow * GST + lcol + q * 4];                     \
            ad[0] = f2t(a4.x); ad[1] = f2t(a4.y);                              \
            ad[2] = f2t(a4.z); ad[3] = f2t(a4.w);                              \
            float4 b4 = *(const float4*)&(BPTR)[(bn + lrow) * DIM + k0 +       \
                                               lcol + q * 4];                  \
            unsigned* bd = &Bs[lrow * GST + lcol + q * 4];                     \
            bd[0] = f2t(b4.x); bd[1] = f2t(b4.y);                              \
            bd[2] = f2t(b4.z); bd[3] = f2t(b4.w);                              \
        }                                                                      \
        __syncthreads();                                                       \
        _Pragma("unroll") for (int k8 = 0; k8 < 4; k8++) {                     \
            unsigned af[4][4], bf[4][2];                                       \
            _Pragma("unroll") for (int mt = 0; mt < 4; mt++) {                 \
                int r = (wm * 64 + mt * 16 + g) * GST + k8 * 8 + tig;          \
                af[mt][0] = As[r];            af[mt][1] = As[r + 8 * GST];     \
                af[mt][2] = As[r + 4];        af[mt][3] = As[r + 8 * GST + 4]; \
            }                                                                  \
            _Pragma("unroll") for (int nt = 0; nt < 4; nt++) {                 \
                int r = (wn * 32 + nt * 8 + g) * GST + k8 * 8 + tig;           \
                bf[nt][0] = Bs[r]; bf[nt][1] = Bs[r + 4];                      \
            }                                                                  \
            _Pragma("unroll") for (int mt = 0; mt < 4; mt++)                   \
                _Pragma("unroll") for (int nt = 0; nt < 4; nt++)               \
                    mma8(acc[mt][nt], af[mt][0], af[mt][1], af[mt][2],         \
                         af[mt][3], bf[nt][0], bf[nt][1]);                     \
        }                                                                      \
        __syncthreads();                                                       \
    }

// ---------------- kernel 2: qkv = x @ W_qkv^T + b + LoRA deltas ----------------
// q -> g_q (fp32, for bias kernels) + g_qh (fp16, pre-scaled by 1/8)
// k -> g_kh (fp16, [head][token][hd])
// v -> g_vh (fp16, TRANSPOSED [head][hd][token])
__global__ __launch_bounds__(256) void qkv_tc_kernel(
    const float* __restrict__ x, const float* __restrict__ W,
    const float* __restrict__ b, const float* __restrict__ Bq,
    const float* __restrict__ Bv) {
    GEMM_MAINLOOP(x, W)
    int which = bn / DIM;
    int hb = bn - which * DIM;
#pragma unroll
    for (int mt = 0; mt < 4; mt++) {
#pragma unroll
        for (int h = 0; h < 2; h++) {
            int m = bm + wm * 64 + mt * 16 + g + 8 * h;
            float4 t4 = {0.f, 0.f, 0.f, 0.f};
            if (which == 0) t4 = *(const float4*)&g_tq[m * RANK];
            if (which == 2) t4 = *(const float4*)&g_tv[m * RANK];
#pragma unroll
            for (int nt = 0; nt < 4; nt++) {
                int cb = wn * 32 + nt * 8 + 2 * tig;
                int hcol = hb + cb;
                int head = hcol >> 6, c = hcol & 63;
                float v0 = acc[mt][nt][2 * h + 0] + b[bn + cb];
                float v1 = acc[mt][nt][2 * h + 1] + b[bn + cb + 1];
                if (which != 1) {
                    const float* Bp = ((which == 0) ? Bq : Bv) + hcol * RANK;
                    v0 += 0.25f * (t4.x * Bp[0] + t4.y * Bp[1] +
                                   t4.z * Bp[2] + t4.w * Bp[3]);
                    v1 += 0.25f * (t4.x * Bp[4] + t4.y * Bp[5] +
                                   t4.z * Bp[6] + t4.w * Bp[7]);
                }
                if (which == 0) {
                    float2 o2 = {v0, v1};
                    *(float2*)&g_q[head * (NTOK * HD) + m * HD + c] = o2;
                    *(unsigned*)&g_qh[head * (NTOK * HD) + m * HD + c] =
                        packh2(v0 * 0.125f, v1 * 0.125f);
                } else if (which == 1) {
                    *(unsigned*)&g_kh[head * (NTOK * HD) + m * HD + c] =
                        packh2(v0, v1);
                } else {
                    __half* vp = &g_vh[head * (HD * NTOK)];
                    vp[c * NTOK + m] = __float2half_rn(v0);
                    vp[(c + 1) * NTOK + m] = __float2half_rn(v1);
                }
            }
        }
    }
}

// ---------------- kernel 5: out = O @ W_proj^T + b_proj ----------------
__global__ __launch_bounds__(256) void proj_tc_kernel(
    const float* __restrict__ W, const float* __restrict__ bp,
    float* __restrict__ out) {
    GEMM_MAINLOOP(g_o, W)
#pragma unroll
    for (int mt = 0; mt < 4; mt++) {
#pragma unroll
        for (int h = 0; h < 2; h++) {
            int m = bm + wm * 64 + mt * 16 + g + 8 * h;
#pragma unroll
            for (int nt = 0; nt < 4; nt++) {
                int n = bn + wn * 32 + nt * 8 + 2 * tig;
                float2 o2 = {acc[mt][nt][2 * h + 0] + bp[n],
                             acc[mt][nt][2 * h + 1] + bp[n + 1]};
                *(float2*)&out[m * DIM + n] = o2;
            }
        }
    }
}

// ---------------- kernel 3: decomposed rel-pos biases as 64x64x64 GEMM blocks --
__global__ __launch_bounds__(256) void bias2_kernel(
    const float* __restrict__ rel, int mode) {
    float* outg = mode ? g_bw : g_bh;
    __shared__ float Qs[64][68];
    __shared__ float Rs[64][68];
    int f = blockIdx.x;
    int head = blockIdx.y;
    int tid = threadIdx.x;
    int row = tid >> 2, cb = (tid & 3) * 16;
    int gi = (mode == 0) ? (f * 64 + row) : (row * 64 + f);
    const float* qp = &g_q[head * (NTOK * HD) + gi * HD + cb];
    const float* rp = &rel[(f + 63 - row) * HD + cb];
#pragma unroll
    for (int q4 = 0; q4 < 4; q4++) {
        float4 qv = *(const float4*)&qp[q4 * 4];
        float4 rv = *(const float4*)&rp[q4 * 4];
        int c = cb + q4 * 4;
        Qs[c + 0][row] = qv.x; Qs[c + 1][row] = qv.y;
        Qs[c + 2][row] = qv.z; Qs[c + 3][row] = qv.w;
        Rs[c + 0][row] = rv.x; Rs[c + 1][row] = rv.y;
        Rs[c + 2][row] = rv.z; Rs[c + 3][row] = rv.w;
    }
    __syncthreads();
    int tx = tid & 15, ty = tid >> 4;
    float s[4][4] = {};
#pragma unroll
    for (int c = 0; c < 64; c++) {
        float4 a4 = *(const float4*)&Qs[c][ty * 4];
        float4 b4 = *(const float4*)&Rs[c][tx * 4];
        float a[4] = {a4.x, a4.y, a4.z, a4.w};
        float bb[4] = {b4.x, b4.y, b4.z, b4.w};
#pragma unroll
        for (int i = 0; i < 4; i++)
#pragma unroll
            for (int j = 0; j < 4; j++) s[i][j] += a[i] * bb[j];
    }
#pragma unroll
    for (int i = 0; i < 4; i++) {
        int t = ty * 4 + i;
        int ig = (mode == 0) ? (f * 64 + t) : (t * 64 + f);
        float4 o4 = {s[i][0], s[i][1], s[i][2], s[i][3]};
        *(float4*)&outg[head * (NTOK * 64) + ig * 64 + tx * 4] = o4;
    }
}

// ---------------- kernel 4: flash attention, fp16 m16n8k16 ----------------
// R6 shape (128 threads, 64-row q tile, 2+ CTAs/SM) with fp16 fragments:
// half the MMAs, half the LDS, half the smem of the tf32 version.
// V arrives pre-transposed from qkv so PV B-frags are contiguous half2 pairs.
#define KH_ST 72  // halves per row (64 + 8 pad) -> conflict-free frag loads
__global__ __launch_bounds__(128) void attn_kernel() {
    __shared__ __half Ks[64 * KH_ST];  // [key][hd]
    __shared__ __half Vt[64 * KH_ST];  // [hd][key]
    __shared__ __half Ps[64 * KH_ST];  // [qrow][key]

    int head = blockIdx.y;
    int q0 = blockIdx.x * 64;
    int tid = threadIdx.x;
    int warp = tid >> 5, lane = tid & 31;
    int g = lane >> 2, tig = lane & 3;
    int r0 = warp * 16 + g, r1 = r0 + 8;

    const __half* qh = g_qh + head * (NTOK * HD) + q0 * HD;
    const __half* kh = g_kh + head * (NTOK * HD);
    const __half* vh = g_vh + head * (HD * NTOK);
    const float* bhg = g_bh + head * (NTOK * 64);
    const float* bwg = g_bw + head * (NTOK * 64);

    // Q fragments (fp16, pre-scaled by 1/8 in qkv): 4 k-steps x 4 regs
    unsigned qf[4][4];
#pragma unroll
    for (int kk = 0; kk < 4; kk++) {
        qf[kk][0] = *(const unsigned*)&qh[r0 * 64 + kk * 16 + 2 * tig];
        qf[kk][1] = *(const unsigned*)&qh[r1 * 64 + kk * 16 + 2 * tig];
        qf[kk][2] = *(const unsigned*)&qh[r0 * 64 + kk * 16 + 2 * tig + 8];
        qf[kk][3] = *(const unsigned*)&qh[r1 * 64 + kk * 16 + 2 * tig + 8];
    }
    // bias_w: loop-invariant over key tiles
    float bw0[16], bw1[16];
#pragma unroll
    for (int jj = 0; jj < 8; jj++) {
        float2 t0 = *(const float2*)&bwg[(q0 + r0) * 64 + jj * 8 + 2 * tig];
        float2 t1 = *(const float2*)&bwg[(q0 + r1) * 64 + jj * 8 + 2 * tig];
        bw0[2 * jj] = t0.x; bw0[2 * jj + 1] = t0.y;
        bw1[2 * jj] = t1.x; bw1[2 * jj + 1] = t1.y;
    }

    float oac[8][4] = {};
    float m0 = -1e30f, m1 = -1e30f, l0 = 0.f, l1 = 0.f;

    for (int kt = 0; kt < 64; kt++) {
        __syncthreads();  // prior K/V/P reads complete before overwrite
        // copy K (row=key) and V (row=hd, already transposed) tiles: 128B rows
#pragma unroll
        for (int l = 0; l < 512; l += 128) {
            int cc = l + tid;
            int j = cc >> 3, cb = (cc & 7) * 8;
            *(uint4*)&Ks[j * KH_ST + cb] =
                *(const uint4*)&kh[(kt * 64 + j) * 64 + cb];
            *(uint4*)&Vt[j * KH_ST + cb] =
                *(const uint4*)&vh[j * NTOK + kt * 64 + cb];
        }
        __syncthreads();

        // S = (Q/8) . K^T   (4 k-steps of 16)
        float sac[8][4] = {};
#pragma unroll
        for (int kk = 0; kk < 4; kk++) {
#pragma unroll
            for (int jj = 0; jj < 8; jj++) {
                unsigned b0 =
                    *(const unsigned*)&Ks[(jj * 8 + g) * KH_ST + kk * 16 + 2 * tig];
                unsigned b1 =
                    *(const unsigned*)&Ks[(jj * 8 + g) * KH_ST + kk * 16 + 2 * tig + 8];
                mma16(sac[jj], qf[kk][0], qf[kk][1], qf[kk][2], qf[kk][3], b0, b1);
            }
        }

        // biases + online softmax
        float bh0 = __ldg(&bhg[(q0 + r0) * 64 + kt]);
        float bh1 = __ldg(&bhg[(q0 + r1) * 64 + kt]);
        float mt0 = -1e30f, mt1 = -1e30f;
#pragma unroll
        for (int jj = 0; jj < 8; jj++) {
            sac[jj][0] += bh0 + bw0[2 * jj];
            sac[jj][1] += bh0 + bw0[2 * jj + 1];
            sac[jj][2] += bh1 + bw1[2 * jj];
            sac[jj][3] += bh1 + bw1[2 * jj + 1];
            mt0 = fmaxf(mt0, fmaxf(sac[jj][0], sac[jj][1]));
            mt1 = fmaxf(mt1, fmaxf(sac[jj][2], sac[jj][3]));
        }
#pragma unroll
        for (int o = 1; o < 4; o <<= 1) {
            mt0 = fmaxf(mt0, __shfl_xor_sync(0xffffffffu, mt0, o));
            mt1 = fmaxf(mt1, __shfl_xor_sync(0xffffffffu, mt1, o));
        }
        float mn0 = fmaxf(m0, mt0), mn1 = fmaxf(m1, mt1);
        float c0 = __expf(m0 - mn0), c1 = __expf(m1 - mn1);
        float s0 = 0.f, s1 = 0.f;
#pragma unroll
        for (int jj = 0; jj < 8; jj++) {
            sac[jj][0] = __expf(sac[jj][0] - mn0);
            sac[jj][1] = __expf(sac[jj][1] - mn0);
            sac[jj][2] = __expf(sac[jj][2] - mn1);
            sac[jj][3] = __expf(sac[jj][3] - mn1);
            s0 += sac[jj][0] + sac[jj][1];
            s1 += sac[jj][2] + sac[jj][3];
        }
#pragma unroll
        for (int o = 1; o < 4; o <<= 1) {
            s0 += __shfl_xor_sync(0xffffffffu, s0, o);
            s1 += __shfl_xor_sync(0xffffffffu, s1, o);
        }
        l0 = l0 * c0 + s0; l1 = l1 * c1 + s1;
        m0 = mn0; m1 = mn1;
#pragma unroll
        for (int jj = 0; jj < 8; jj++) {
            oac[jj][0] *= c0; oac[jj][1] *= c0;
            oac[jj][2] *= c1; oac[jj][3] *= c1;
        }

        // store P (fp16 pairs) — each warp touches only its own 16 rows
#pragma unroll
        for (int jj = 0; jj < 8; jj++) {
            *(unsigned*)&Ps[r0 * KH_ST + jj * 8 + 2 * tig] =
                packh2(sac[jj][0], sac[jj][1]);
            *(unsigned*)&Ps[r1 * KH_ST + jj * 8 + 2 * tig] =
                packh2(sac[jj][2], sac[jj][3]);
        }
        __syncwarp();  // warp-local: A-frags below read only this warp's rows

        // O += P @ V   (4 k-steps of 16)
#pragma unroll
        for (int kk = 0; kk < 4; kk++) {
            unsigned a0 = *(const unsigned*)&Ps[r0 * KH_ST + kk * 16 + 2 * tig];
            unsigned a1 = *(const unsigned*)&Ps[r1 * KH_ST + kk * 16 + 2 * tig];
            unsigned a2 = *(const unsigned*)&Ps[r0 * KH_ST + kk * 16 + 2 * tig + 8];
            unsigned a3 = *(const unsigned*)&Ps[r1 * KH_ST + kk * 16 + 2 * tig + 8];
#pragma unroll
            for (int jj = 0; jj < 8; jj++) {
                unsigned b0 =
                    *(const unsigned*)&Vt[(jj * 8 + g) * KH_ST + kk * 16 + 2 * tig];
                unsigned b1 =
                    *(const unsigned*)&Vt[(jj * 8 + g) * KH_ST + kk * 16 + 2 * tig + 8];
                mma16(oac[jj], a0, a1, a2, a3, b0, b1);
            }
        }
    }

    float inv0 = 1.f / l0, inv1 = 1.f / l1;
#pragma unroll
    for (int jj = 0; jj < 8; jj++) {
        int c = head * 64 + jj * 8 + 2 * tig;
        float2 o0 = {oac[jj][0] * inv0, oac[jj][1] * inv0};
        float2 o1 = {oac[jj][2] * inv1, oac[jj][3] * inv1};
        *(float2*)&g_o[(q0 + r0) * DIM + c] = o0;
        *(float2*)&g_o[(q0 + r1) * DIM + c] = o1;
    }
}

extern "C" void kernel_launch(void* const* d_in, const int* in_sizes, int n_in,
                              void* d_out, int out_size) {
    const float* x      = (const float*)d_in[0];
    const float* W_qkv  = (const float*)d_in[1];
    const float* b_qkv  = (const float*)d_in[2];
    const float* A_q    = (const float*)d_in[3];
    const float* B_q    = (const float*)d_in[4];
    const float* A_v    = (const float*)d_in[5];
    const float* B_v    = (const float*)d_in[6];
    const float* rel_h  = (const float*)d_in[7];
    const float* rel_w  = (const float*)d_in[8];
    const float* W_proj = (const float*)d_in[9];
    const float* b_proj = (const float*)d_in[10];
    float* out = (float*)d_out;

    lora_t_kernel<<<512, 256>>>(x, A_q, A_v);
    qkv_tc_kernel<<<dim3(18, 32), 256>>>(x, W_qkv, b_qkv, B_q, B_v);
    bias2_kernel<<<dim3(64, 12), 256>>>(rel_h, 0);
    bias2_kernel<<<dim3(64, 12), 256>>>(rel_w, 1);
    attn_kernel<<<dim3(64, 12), 128>>>();
    proj_tc_kernel<<<dim3(6, 32), 256>>>(W_proj, b_proj, out);
}

// round 16
// speedup vs baseline: 1.6442x; 1.0570x over previous
#include <cuda_runtime.h>
#include <cuda_fp16.h>
#include <cstdint>

#define NTOK 4096
#define DIM 768
#define NH 12
#define HD 64
#define RANK 4

// scratch (device globals: no allocation allowed)
__device__ float g_q[NH * NTOK * HD];          // fp32 q (bias kernels)
__device__ __half g_qh[NH * NTOK * HD];        // fp16 q, pre-scaled by 1/8
__device__ __half g_kh[NH * NTOK * HD];        // fp16 k, [head][token][hd]
__device__ __half g_vh[NH * HD * NTOK];        // fp16 v, TRANSPOSED [head][hd][token]
__device__ float g_tq[NTOK * RANK];
__device__ float g_tv[NTOK * RANK];
__device__ float g_bh[NH * NTOK * 64];
__device__ float g_bw[NH * NTOK * 64];
__device__ float g_o[NTOK * DIM];

__device__ __forceinline__ unsigned packh2(float lo, float hi) {
    unsigned r;
    asm("cvt.rn.f16x2.f32 %0, %1, %2;" : "=r"(r) : "f"(hi), "f"(lo));
    return r;
}
__device__ __forceinline__ void mma16(float* c, unsigned a0, unsigned a1,
                                      unsigned a2, unsigned a3, unsigned b0,
                                      unsigned b1) {
    asm("mma.sync.aligned.m16n8k16.row.col.f32.f16.f16.f32 "
        "{%0,%1,%2,%3},{%4,%5,%6,%7},{%8,%9},{%0,%1,%2,%3};"
        : "+f"(c[0]), "+f"(c[1]), "+f"(c[2]), "+f"(c[3])
        : "r"(a0), "r"(a1), "r"(a2), "r"(a3), "r"(b0), "r"(b1));
}

// ---------------- kernel 1: t = x @ A^T (rank-4 LoRA down-proj) ----------------
__global__ void lora_t_kernel(const float* __restrict__ x,
                              const float* __restrict__ Aq,
                              const float* __restrict__ Av) {
    int warp = (blockIdx.x * blockDim.x + threadIdx.x) >> 5;
    int lane = threadIdx.x & 31;
    if (warp >= NTOK) return;
    const float* xr = x + warp * DIM;
    float p[8] = {0.f, 0.f, 0.f, 0.f, 0.f, 0.f, 0.f, 0.f};
    for (int i = lane; i < DIM; i += 32) {
        float xv = xr[i];
#pragma unroll
        for (int r = 0; r < RANK; r++) {
            p[r]        += xv * Aq[r * DIM + i];
            p[RANK + r] += xv * Av[r * DIM + i];
        }
    }
#pragma unroll
    for (int r = 0; r < 8; r++) {
#pragma unroll
        for (int o = 16; o; o >>= 1)
            p[r] += __shfl_xor_sync(0xffffffffu, p[r], o);
    }
    if (lane == 0) {
#pragma unroll
        for (int r = 0; r < RANK; r++) {
            g_tq[warp * RANK + r] = p[r];
            g_tv[warp * RANK + r] = p[RANK + r];
        }
    }
}

// ---------------- fp16 GEMM mainloop (shared by qkv/proj) ----------------
// 128x128 tile, BK=32, 256 threads = 8 warps, warp tile 64x32 (m16n8k16 2x4x4).
// A[M,K] row-major, B[N,K] row-major (NT), fp32 in -> half2 packed in smem.
// Row stride 40 halves (20 words): fragment loads (20*g + tig) mod 32 all
// distinct -> conflict-free.
#define HST 40
#define GEMM_MAINLOOP_H(APTR, BPTR)                                            \
    __shared__ __half As[128 * HST];                                           \
    __shared__ __half Bs[128 * HST];                                           \
    int tid = threadIdx.x;                                                     \
    int warp = tid >> 5, lane = tid & 31;                                      \
    int g = lane >> 2, tig = lane & 3;                                         \
    int wm = warp & 1, wn = warp >> 1;                                         \
    int bm = blockIdx.y * 128, bn = blockIdx.x * 128;                          \
    int lrow = tid >> 1, lc = (tid & 1) * 16;                                  \
    float acc[4][4][4] = {};                                                   \
    for (int k0 = 0; k0 < DIM; k0 += 32) {                                     \
        unsigned pa[8], pb[8];                                                 \
        _Pragma("unroll") for (int q = 0; q < 4; q++) {                        \
            float4 a4 = *(const float4*)&(APTR)[(bm + lrow) * DIM + k0 + lc +  \
                                               q * 4];                         \
            pa[2 * q] = packh2(a4.x, a4.y);                                    \
            pa[2 * q + 1] = packh2(a4.z, a4.w);                                \
            float4 b4 = *(const float4*)&(BPTR)[(bn + lrow) * DIM + k0 + lc +  \
                                               q * 4];                         \
            pb[2 * q] = packh2(b4.x, b4.y);                                    \
            pb[2 * q + 1] = packh2(b4.z, b4.w);                                \
        }                                                                      \
        *(uint4*)&As[lrow * HST + lc] = make_uint4(pa[0], pa[1], pa[2], pa[3]);\
        *(uint4*)&As[lrow * HST + lc + 8] =                                    \
            make_uint4(pa[4], pa[5], pa[6], pa[7]);                            \
        *(uint4*)&Bs[lrow * HST + lc] = make_uint4(pb[0], pb[1], pb[2], pb[3]);\
        *(uint4*)&Bs[lrow * HST + lc + 8] =                                    \
            make_uint4(pb[4], pb[5], pb[6], pb[7]);                            \
        __syncthreads();                                                       \
        _Pragma("unroll") for (int kk = 0; kk < 2; kk++) {                     \
            unsigned af[4][4], bf[4][2];                                       \
            _Pragma("unroll") for (int mt = 0; mt < 4; mt++) {                 \
                int r = (wm * 64 + mt * 16 + g) * HST + kk * 16 + 2 * tig;     \
                af[mt][0] = *(const unsigned*)&As[r];                          \
                af[mt][1] = *(const unsigned*)&As[r + 8 * HST];                \
                af[mt][2] = *(const unsigned*)&As[r + 8];                      \
                af[mt][3] = *(const unsigned*)&As[r + 8 * HST + 8];            \
            }                                                                  \
            _Pragma("unroll") for (int nt = 0; nt < 4; nt++) {                 \
                int r = (wn * 32 + nt * 8 + g) * HST + kk * 16 + 2 * tig;      \
                bf[nt][0] = *(const unsigned*)&Bs[r];                          \
                bf[nt][1] = *(const unsigned*)&Bs[r + 8];                      \
            }                                                                  \
            _Pragma("unroll") for (int mt = 0; mt < 4; mt++)                   \
                _Pragma("unroll") for (int nt = 0; nt < 4; nt++)               \
                    mma16(acc[mt][nt], af[mt][0], af[mt][1], af[mt][2],        \
                          af[mt][3], bf[nt][0], bf[nt][1]);                    \
        }                                                                      \
        __syncthreads();                                                       \
    }

// ---------------- kernel 2: qkv = x @ W_qkv^T + b + LoRA deltas ----------------
// q -> g_q (fp32, for bias kernels) + g_qh (fp16, pre-scaled by 1/8)
// k -> g_kh (fp16, [head][token][hd])
// v -> g_vh (fp16, TRANSPOSED [head][hd][token])
__global__ __launch_bounds__(256) void qkv_tc_kernel(
    const float* __restrict__ x, const float* __restrict__ W,
    const float* __restrict__ b, const float* __restrict__ Bq,
    const float* __restrict__ Bv) {
    GEMM_MAINLOOP_H(x, W)
    int which = bn / DIM;
    int hb = bn - which * DIM;
#pragma unroll
    for (int mt = 0; mt < 4; mt++) {
#pragma unroll
        for (int h = 0; h < 2; h++) {
            int m = bm + wm * 64 + mt * 16 + g + 8 * h;
            float4 t4 = {0.f, 0.f, 0.f, 0.f};
            if (which == 0) t4 = *(const float4*)&g_tq[m * RANK];
            if (which == 2) t4 = *(const float4*)&g_tv[m * RANK];
#pragma unroll
            for (int nt = 0; nt < 4; nt++) {
                int cb = wn * 32 + nt * 8 + 2 * tig;
                int hcol = hb + cb;
                int head = hcol >> 6, c = hcol & 63;
                float v0 = acc[mt][nt][2 * h + 0] + b[bn + cb];
                float v1 = acc[mt][nt][2 * h + 1] + b[bn + cb + 1];
                if (which != 1) {
                    const float* Bp = ((which == 0) ? Bq : Bv) + hcol * RANK;
                    v0 += 0.25f * (t4.x * Bp[0] + t4.y * Bp[1] +
                                   t4.z * Bp[2] + t4.w * Bp[3]);
                    v1 += 0.25f * (t4.x * Bp[4] + t4.y * Bp[5] +
                                   t4.z * Bp[6] + t4.w * Bp[7]);
                }
                if (which == 0) {
                    float2 o2 = {v0, v1};
                    *(float2*)&g_q[head * (NTOK * HD) + m * HD + c] = o2;
                    *(unsigned*)&g_qh[head * (NTOK * HD) + m * HD + c] =
                        packh2(v0 * 0.125f, v1 * 0.125f);
                } else if (which == 1) {
                    *(unsigned*)&g_kh[head * (NTOK * HD) + m * HD + c] =
                        packh2(v0, v1);
                } else {
                    __half* vp = &g_vh[head * (HD * NTOK)];
                    vp[c * NTOK + m] = __float2half_rn(v0);
                    vp[(c + 1) * NTOK + m] = __float2half_rn(v1);
                }
            }
        }
    }
}

// ---------------- kernel 5: out = O @ W_proj^T + b_proj ----------------
__global__ __launch_bounds__(256) void proj_tc_kernel(
    const float* __restrict__ W, const float* __restrict__ bp,
    float* __restrict__ out) {
    GEMM_MAINLOOP_H(g_o, W)
#pragma unroll
    for (int mt = 0; mt < 4; mt++) {
#pragma unroll
        for (int h = 0; h < 2; h++) {
            int m = bm + wm * 64 + mt * 16 + g + 8 * h;
#pragma unroll
            for (int nt = 0; nt < 4; nt++) {
                int n = bn + wn * 32 + nt * 8 + 2 * tig;
                float2 o2 = {acc[mt][nt][2 * h + 0] + bp[n],
                             acc[mt][nt][2 * h + 1] + bp[n + 1]};
                *(float2*)&out[m * DIM + n] = o2;
            }
        }
    }
}

// ---------------- kernel 3: decomposed rel-pos biases as 64x64x64 GEMM blocks --
__global__ __launch_bounds__(256) void bias2_kernel(
    const float* __restrict__ rel, int mode) {
    float* outg = mode ? g_bw : g_bh;
    __shared__ float Qs[64][68];
    __shared__ float Rs[64][68];
    int f = blockIdx.x;
    int head = blockIdx.y;
    int tid = threadIdx.x;
    int row = tid >> 2, cb = (tid & 3) * 16;
    int gi = (mode == 0) ? (f * 64 + row) : (row * 64 + f);
    const float* qp = &g_q[head * (NTOK * HD) + gi * HD + cb];
    const float* rp = &rel[(f + 63 - row) * HD + cb];
#pragma unroll
    for (int q4 = 0; q4 < 4; q4++) {
        float4 qv = *(const float4*)&qp[q4 * 4];
        float4 rv = *(const float4*)&rp[q4 * 4];
        int c = cb + q4 * 4;
        Qs[c + 0][row] = qv.x; Qs[c + 1][row] = qv.y;
        Qs[c + 2][row] = qv.z; Qs[c + 3][row] = qv.w;
        Rs[c + 0][row] = rv.x; Rs[c + 1][row] = rv.y;
        Rs[c + 2][row] = rv.z; Rs[c + 3][row] = rv.w;
    }
    __syncthreads();
    int tx = tid & 15, ty = tid >> 4;
    float s[4][4] = {};
#pragma unroll
    for (int c = 0; c < 64; c++) {
        float4 a4 = *(const float4*)&Qs[c][ty * 4];
        float4 b4 = *(const float4*)&Rs[c][tx * 4];
        float a[4] = {a4.x, a4.y, a4.z, a4.w};
        float bb[4] = {b4.x, b4.y, b4.z, b4.w};
#pragma unroll
        for (int i = 0; i < 4; i++)
#pragma unroll
            for (int j = 0; j < 4; j++) s[i][j] += a[i] * bb[j];
    }
#pragma unroll
    for (int i = 0; i < 4; i++) {
        int t = ty * 4 + i;
        int ig = (mode == 0) ? (f * 64 + t) : (t * 64 + f);
        float4 o4 = {s[i][0], s[i][1], s[i][2], s[i][3]};
        *(float4*)&outg[head * (NTOK * 64) + ig * 64 + tx * 4] = o4;
    }
}

// ---------------- kernel 4: flash attention, fp16 m16n8k16 ----------------
#define KH_ST 72  // halves per row (64 + 8 pad) -> conflict-free frag loads
__global__ __launch_bounds__(128) void attn_kernel() {
    __shared__ __half Ks[64 * KH_ST];  // [key][hd]
    __shared__ __half Vt[64 * KH_ST];  // [hd][key]
    __shared__ __half Ps[64 * KH_ST];  // [qrow][key]

    int head = blockIdx.y;
    int q0 = blockIdx.x * 64;
    int tid = threadIdx.x;
    int warp = tid >> 5, lane = tid & 31;
    int g = lane >> 2, tig = lane & 3;
    int r0 = warp * 16 + g, r1 = r0 + 8;

    const __half* qh = g_qh + head * (NTOK * HD) + q0 * HD;
    const __half* kh = g_kh + head * (NTOK * HD);
    const __half* vh = g_vh + head * (HD * NTOK);
    const float* bhg = g_bh + head * (NTOK * 64);
    const float* bwg = g_bw + head * (NTOK * 64);

    unsigned qf[4][4];
#pragma unroll
    for (int kk = 0; kk < 4; kk++) {
        qf[kk][0] = *(const unsigned*)&qh[r0 * 64 + kk * 16 + 2 * tig];
        qf[kk][1] = *(const unsigned*)&qh[r1 * 64 + kk * 16 + 2 * tig];
        qf[kk][2] = *(const unsigned*)&qh[r0 * 64 + kk * 16 + 2 * tig + 8];
        qf[kk][3] = *(const unsigned*)&qh[r1 * 64 + kk * 16 + 2 * tig + 8];
    }
    float bw0[16], bw1[16];
#pragma unroll
    for (int jj = 0; jj < 8; jj++) {
        float2 t0 = *(const float2*)&bwg[(q0 + r0) * 64 + jj * 8 + 2 * tig];
        float2 t1 = *(const float2*)&bwg[(q0 + r1) * 64 + jj * 8 + 2 * tig];
        bw0[2 * jj] = t0.x; bw0[2 * jj + 1] = t0.y;
        bw1[2 * jj] = t1.x; bw1[2 * jj + 1] = t1.y;
    }

    float oac[8][4] = {};
    float m0 = -1e30f, m1 = -1e30f, l0 = 0.f, l1 = 0.f;

    for (int kt = 0; kt < 64; kt++) {
        __syncthreads();
#pragma unroll
        for (int l = 0; l < 512; l += 128) {
            int cc = l + tid;
            int j = cc >> 3, cb = (cc & 7) * 8;
            *(uint4*)&Ks[j * KH_ST + cb] =
                *(const uint4*)&kh[(kt * 64 + j) * 64 + cb];
            *(uint4*)&Vt[j * KH_ST + cb] =
                *(const uint4*)&vh[j * NTOK + kt * 64 + cb];
        }
        __syncthreads();

        // S = (Q/8) . K^T   (4 k-steps of 16)
        float sac[8][4] = {};
#pragma unroll
        for (int kk = 0; kk < 4; kk++) {
#pragma unroll
            for (int jj = 0; jj < 8; jj++) {
                unsigned b0 =
                    *(const unsigned*)&Ks[(jj * 8 + g) * KH_ST + kk * 16 + 2 * tig];
                unsigned b1 =
                    *(const unsigned*)&Ks[(jj * 8 + g) * KH_ST + kk * 16 + 2 * tig + 8];
                mma16(sac[jj], qf[kk][0], qf[kk][1], qf[kk][2], qf[kk][3], b0, b1);
            }
        }

        float bh0 = __ldg(&bhg[(q0 + r0) * 64 + kt]);
        float bh1 = __ldg(&bhg[(q0 + r1) * 64 + kt]);
        float mt0 = -1e30f, mt1 = -1e30f;
#pragma unroll
        for (int jj = 0; jj < 8; jj++) {
            sac[jj][0] += bh0 + bw0[2 * jj];
            sac[jj][1] += bh0 + bw0[2 * jj + 1];
            sac[jj][2] += bh1 + bw1[2 * jj];
            sac[jj][3] += bh1 + bw1[2 * jj + 1];
            mt0 = fmaxf(mt0, fmaxf(sac[jj][0], sac[jj][1]));
            mt1 = fmaxf(mt1, fmaxf(sac[jj][2], sac[jj][3]));
        }
#pragma unroll
        for (int o = 1; o < 4; o <<= 1) {
            mt0 = fmaxf(mt0, __shfl_xor_sync(0xffffffffu, mt0, o));
            mt1 = fmaxf(mt1, __shfl_xor_sync(0xffffffffu, mt1, o));
        }
        float mn0 = fmaxf(m0, mt0), mn1 = fmaxf(m1, mt1);
        float c0 = __expf(m0 - mn0), c1 = __expf(m1 - mn1);
        float s0 = 0.f, s1 = 0.f;
#pragma unroll
        for (int jj = 0; jj < 8; jj++) {
            sac[jj][0] = __expf(sac[jj][0] - mn0);
            sac[jj][1] = __expf(sac[jj][1] - mn0);
            sac[jj][2] = __expf(sac[jj][2] - mn1);
            sac[jj][3] = __expf(sac[jj][3] - mn1);
            s0 += sac[jj][0] + sac[jj][1];
            s1 += sac[jj][2] + sac[jj][3];
        }
#pragma unroll
        for (int o = 1; o < 4; o <<= 1) {
            s0 += __shfl_xor_sync(0xffffffffu, s0, o);
            s1 += __shfl_xor_sync(0xffffffffu, s1, o);
        }
        l0 = l0 * c0 + s0; l1 = l1 * c1 + s1;
        m0 = mn0; m1 = mn1;
#pragma unroll
        for (int jj = 0; jj < 8; jj++) {
            oac[jj][0] *= c0; oac[jj][1] *= c0;
            oac[jj][2] *= c1; oac[jj][3] *= c1;
        }

#pragma unroll
        for (int jj = 0; jj < 8; jj++) {
            *(unsigned*)&Ps[r0 * KH_ST + jj * 8 + 2 * tig] =
                packh2(sac[jj][0], sac[jj][1]);
            *(unsigned*)&Ps[r1 * KH_ST + jj * 8 + 2 * tig] =
                packh2(sac[jj][2], sac[jj][3]);
        }
        __syncwarp();

        // O += P @ V   (4 k-steps of 16)
#pragma unroll
        for (int kk = 0; kk < 4; kk++) {
            unsigned a0 = *(const unsigned*)&Ps[r0 * KH_ST + kk * 16 + 2 * tig];
            unsigned a1 = *(const unsigned*)&Ps[r1 * KH_ST + kk * 16 + 2 * tig];
            unsigned a2 = *(const unsigned*)&Ps[r0 * KH_ST + kk * 16 + 2 * tig + 8];
            unsigned a3 = *(const unsigned*)&Ps[r1 * KH_ST + kk * 16 + 2 * tig + 8];
#pragma unroll
            for (int jj = 0; jj < 8; jj++) {
                unsigned b0 =
                    *(const unsigned*)&Vt[(jj * 8 + g) * KH_ST + kk * 16 + 2 * tig];
                unsigned b1 =
                    *(const unsigned*)&Vt[(jj * 8 + g) * KH_ST + kk * 16 + 2 * tig + 8];
                mma16(oac[jj], a0, a1, a2, a3, b0, b1);
            }
        }
    }

    float inv0 = 1.f / l0, inv1 = 1.f / l1;
#pragma unroll
    for (int jj = 0; jj < 8; jj++) {
        int c = head * 64 + jj * 8 + 2 * tig;
        float2 o0 = {oac[jj][0] * inv0, oac[jj][1] * inv0};
        float2 o1 = {oac[jj][2] * inv1, oac[jj][3] * inv1};
        *(float2*)&g_o[(q0 + r0) * DIM + c] = o0;
        *(float2*)&g_o[(q0 + r1) * DIM + c] = o1;
    }
}

extern "C" void kernel_launch(void* const* d_in, const int* in_sizes, int n_in,
                              void* d_out, int out_size) {
    const float* x      = (const float*)d_in[0];
    const float* W_qkv  = (const float*)d_in[1];
    const float* b_qkv  = (const float*)d_in[2];
    const float* A_q    = (const float*)d_in[3];
    const float* B_q    = (const float*)d_in[4];
    const float* A_v    = (const float*)d_in[5];
    const float* B_v    = (const float*)d_in[6];
    const float* rel_h  = (const float*)d_in[7];
    const float* rel_w  = (const float*)d_in[8];
    const float* W_proj = (const float*)d_in[9];
    const float* b_proj = (const float*)d_in[10];
    float* out = (float*)d_out;

    lora_t_kernel<<<512, 256>>>(x, A_q, A_v);
    qkv_tc_kernel<<<dim3(18, 32), 256>>>(x, W_qkv, b_qkv, B_q, B_v);
    bias2_kernel<<<dim3(64, 12), 256>>>(rel_h, 0);
    bias2_kernel<<<dim3(64, 12), 256>>>(rel_w, 1);
    attn_kernel<<<dim3(64, 12), 128>>>();
    proj_tc_kernel<<<dim3(6, 32), 256>>>(W_proj, b_proj, out);
}

// round 17
// speedup vs baseline: 1.7767x; 1.0805x over previous
#include <cuda_runtime.h>
#include <cuda_fp16.h>
#include <cstdint>

#define NTOK 4096
#define DIM 768
#define NH 12
#define HD 64
#define RANK 4

// scratch (device globals: no allocation allowed)
__device__ float g_q[NH * NTOK * HD];          // fp32 q (bias kernels)
__device__ __half g_qh[NH * NTOK * HD];        // fp16 q, pre-scaled by 1/8
__device__ __half g_kh[NH * NTOK * HD];        // fp16 k, [head][token][hd]
__device__ __half g_vh[NH * HD * NTOK];        // fp16 v, TRANSPOSED [head][hd][token]
__device__ float g_tq[NTOK * RANK];
__device__ float g_tv[NTOK * RANK];
__device__ float g_bh[NH * NTOK * 64];
__device__ float g_bw[NH * NTOK * 64];
__device__ float g_o[NTOK * DIM];

__device__ __forceinline__ unsigned packh2(float lo, float hi) {
    unsigned r;
    asm("cvt.rn.f16x2.f32 %0, %1, %2;" : "=r"(r) : "f"(hi), "f"(lo));
    return r;
}
__device__ __forceinline__ void mma16(float* c, unsigned a0, unsigned a1,
                                      unsigned a2, unsigned a3, unsigned b0,
                                      unsigned b1) {
    asm("mma.sync.aligned.m16n8k16.row.col.f32.f16.f16.f32 "
        "{%0,%1,%2,%3},{%4,%5,%6,%7},{%8,%9},{%0,%1,%2,%3};"
        : "+f"(c[0]), "+f"(c[1]), "+f"(c[2]), "+f"(c[3])
        : "r"(a0), "r"(a1), "r"(a2), "r"(a3), "r"(b0), "r"(b1));
}
__device__ __forceinline__ void ldsm4(unsigned& d0, unsigned& d1,
                                      unsigned& d2, unsigned& d3,
                                      uint32_t addr) {
    asm volatile(
        "ldmatrix.sync.aligned.m8n8.x4.shared.b16 {%0,%1,%2,%3}, [%4];"
        : "=r"(d0), "=r"(d1), "=r"(d2), "=r"(d3)
        : "r"(addr));
}

// ---------------- kernel 1: t = x @ A^T (rank-4 LoRA down-proj) ----------------
__global__ void lora_t_kernel(const float* __restrict__ x,
                              const float* __restrict__ Aq,
                              const float* __restrict__ Av) {
    int warp = (blockIdx.x * blockDim.x + threadIdx.x) >> 5;
    int lane = threadIdx.x & 31;
    if (warp >= NTOK) return;
    const float* xr = x + warp * DIM;
    float p[8] = {0.f, 0.f, 0.f, 0.f, 0.f, 0.f, 0.f, 0.f};
    for (int i = lane; i < DIM; i += 32) {
        float xv = xr[i];
#pragma unroll
        for (int r = 0; r < RANK; r++) {
            p[r]        += xv * Aq[r * DIM + i];
            p[RANK + r] += xv * Av[r * DIM + i];
        }
    }
#pragma unroll
    for (int r = 0; r < 8; r++) {
#pragma unroll
        for (int o = 16; o; o >>= 1)
            p[r] += __shfl_xor_sync(0xffffffffu, p[r], o);
    }
    if (lane == 0) {
#pragma unroll
        for (int r = 0; r < RANK; r++) {
            g_tq[warp * RANK + r] = p[r];
            g_tv[warp * RANK + r] = p[RANK + r];
        }
    }
}

// ---------------- fp16 GEMM mainloop (shared by qkv/proj) ----------------
#define HST 40
#define GEMM_MAINLOOP_H(APTR, BPTR)                                            \
    __shared__ __half As[128 * HST];                                           \
    __shared__ __half Bs[128 * HST];                                           \
    int tid = threadIdx.x;                                                     \
    int warp = tid >> 5, lane = tid & 31;                                      \
    int g = lane >> 2, tig = lane & 3;                                         \
    int wm = warp & 1, wn = warp >> 1;                                         \
    int bm = blockIdx.y * 128, bn = blockIdx.x * 128;                          \
    int lrow = tid >> 1, lc = (tid & 1) * 16;                                  \
    float acc[4][4][4] = {};                                                   \
    for (int k0 = 0; k0 < DIM; k0 += 32) {                                     \
        unsigned pa[8], pb[8];                                                 \
        _Pragma("unroll") for (int q = 0; q < 4; q++) {                        \
            float4 a4 = *(const float4*)&(APTR)[(bm + lrow) * DIM + k0 + lc +  \
                                               q * 4];                         \
            pa[2 * q] = packh2(a4.x, a4.y);                                    \
            pa[2 * q + 1] = packh2(a4.z, a4.w);                                \
            float4 b4 = *(const float4*)&(BPTR)[(bn + lrow) * DIM + k0 + lc +  \
                                               q * 4];                         \
            pb[2 * q] = packh2(b4.x, b4.y);                                    \
            pb[2 * q + 1] = packh2(b4.z, b4.w);                                \
        }                                                                      \
        *(uint4*)&As[lrow * HST + lc] = make_uint4(pa[0], pa[1], pa[2], pa[3]);\
        *(uint4*)&As[lrow * HST + lc + 8] =                                    \
            make_uint4(pa[4], pa[5], pa[6], pa[7]);                            \
        *(uint4*)&Bs[lrow * HST + lc] = make_uint4(pb[0], pb[1], pb[2], pb[3]);\
        *(uint4*)&Bs[lrow * HST + lc + 8] =                                    \
            make_uint4(pb[4], pb[5], pb[6], pb[7]);                            \
        __syncthreads();                                                       \
        _Pragma("unroll") for (int kk = 0; kk < 2; kk++) {                     \
            unsigned af[4][4], bf[4][2];                                       \
            _Pragma("unroll") for (int mt = 0; mt < 4; mt++) {                 \
                int r = (wm * 64 + mt * 16 + g) * HST + kk * 16 + 2 * tig;     \
                af[mt][0] = *(const unsigned*)&As[r];                          \
                af[mt][1] = *(const unsigned*)&As[r + 8 * HST];                \
                af[mt][2] = *(const unsigned*)&As[r + 8];                      \
                af[mt][3] = *(const unsigned*)&As[r + 8 * HST + 8];            \
            }                                                                  \
            _Pragma("unroll") for (int nt = 0; nt < 4; nt++) {                 \
                int r = (wn * 32 + nt * 8 + g) * HST + kk * 16 + 2 * tig;      \
                bf[nt][0] = *(const unsigned*)&Bs[r];                          \
                bf[nt][1] = *(const unsigned*)&Bs[r + 8];                      \
            }                                                                  \
            _Pragma("unroll") for (int mt = 0; mt < 4; mt++)                   \
                _Pragma("unroll") for (int nt = 0; nt < 4; nt++)               \
                    mma16(acc[mt][nt], af[mt][0], af[mt][1], af[mt][2],        \
                          af[mt][3], bf[nt][0], bf[nt][1]);                    \
        }                                                                      \
        __syncthreads();                                                       \
    }

// ---------------- kernel 2: qkv = x @ W_qkv^T + b + LoRA deltas ----------------
__global__ __launch_bounds__(256) void qkv_tc_kernel(
    const float* __restrict__ x, const float* __restrict__ W,
    const float* __restrict__ b, const float* __restrict__ Bq,
    const float* __restrict__ Bv) {
    GEMM_MAINLOOP_H(x, W)
    int which = bn / DIM;
    int hb = bn - which * DIM;
#pragma unroll
    for (int mt = 0; mt < 4; mt++) {
#pragma unroll
        for (int h = 0; h < 2; h++) {
            int m = bm + wm * 64 + mt * 16 + g + 8 * h;
            float4 t4 = {0.f, 0.f, 0.f, 0.f};
            if (which == 0) t4 = *(const float4*)&g_tq[m * RANK];
            if (which == 2) t4 = *(const float4*)&g_tv[m * RANK];
#pragma unroll
            for (int nt = 0; nt < 4; nt++) {
                int cb = wn * 32 + nt * 8 + 2 * tig;
                int hcol = hb + cb;
                int head = hcol >> 6, c = hcol & 63;
                float v0 = acc[mt][nt][2 * h + 0] + b[bn + cb];
                float v1 = acc[mt][nt][2 * h + 1] + b[bn + cb + 1];
                if (which != 1) {
                    const float* Bp = ((which == 0) ? Bq : Bv) + hcol * RANK;
                    v0 += 0.25f * (t4.x * Bp[0] + t4.y * Bp[1] +
                                   t4.z * Bp[2] + t4.w * Bp[3]);
                    v1 += 0.25f * (t4.x * Bp[4] + t4.y * Bp[5] +
                                   t4.z * Bp[6] + t4.w * Bp[7]);
                }
                if (which == 0) {
                    float2 o2 = {v0, v1};
                    *(float2*)&g_q[head * (NTOK * HD) + m * HD + c] = o2;
                    *(unsigned*)&g_qh[head * (NTOK * HD) + m * HD + c] =
                        packh2(v0 * 0.125f, v1 * 0.125f);
                } else if (which == 1) {
                    *(unsigned*)&g_kh[head * (NTOK * HD) + m * HD + c] =
                        packh2(v0, v1);
                } else {
                    __half* vp = &g_vh[head * (HD * NTOK)];
                    vp[c * NTOK + m] = __float2half_rn(v0);
                    vp[(c + 1) * NTOK + m] = __float2half_rn(v1);
                }
            }
        }
    }
}

// ---------------- kernel 5: out = O @ W_proj^T + b_proj ----------------
__global__ __launch_bounds__(256) void proj_tc_kernel(
    const float* __restrict__ W, const float* __restrict__ bp,
    float* __restrict__ out) {
    GEMM_MAINLOOP_H(g_o, W)
#pragma unroll
    for (int mt = 0; mt < 4; mt++) {
#pragma unroll
        for (int h = 0; h < 2; h++) {
            int m = bm + wm * 64 + mt * 16 + g + 8 * h;
#pragma unroll
            for (int nt = 0; nt < 4; nt++) {
                int n = bn + wn * 32 + nt * 8 + 2 * tig;
                float2 o2 = {acc[mt][nt][2 * h + 0] + bp[n],
                             acc[mt][nt][2 * h + 1] + bp[n + 1]};
                *(float2*)&out[m * DIM + n] = o2;
            }
        }
    }
}

// ---------------- kernel 3: decomposed rel-pos biases as 64x64x64 GEMM blocks --
__global__ __launch_bounds__(256) void bias2_kernel(
    const float* __restrict__ rel, int mode) {
    float* outg = mode ? g_bw : g_bh;
    __shared__ float Qs[64][68];
    __shared__ float Rs[64][68];
    int f = blockIdx.x;
    int head = blockIdx.y;
    int tid = threadIdx.x;
    int row = tid >> 2, cb = (tid & 3) * 16;
    int gi = (mode == 0) ? (f * 64 + row) : (row * 64 + f);
    const float* qp = &g_q[head * (NTOK * HD) + gi * HD + cb];
    const float* rp = &rel[(f + 63 - row) * HD + cb];
#pragma unroll
    for (int q4 = 0; q4 < 4; q4++) {
        float4 qv = *(const float4*)&qp[q4 * 4];
        float4 rv = *(const float4*)&rp[q4 * 4];
        int c = cb + q4 * 4;
        Qs[c + 0][row] = qv.x; Qs[c + 1][row] = qv.y;
        Qs[c + 2][row] = qv.z; Qs[c + 3][row] = qv.w;
        Rs[c + 0][row] = rv.x; Rs[c + 1][row] = rv.y;
        Rs[c + 2][row] = rv.z; Rs[c + 3][row] = rv.w;
    }
    __syncthreads();
    int tx = tid & 15, ty = tid >> 4;
    float s[4][4] = {};
#pragma unroll
    for (int c = 0; c < 64; c++) {
        float4 a4 = *(const float4*)&Qs[c][ty * 4];
        float4 b4 = *(const float4*)&Rs[c][tx * 4];
        float a[4] = {a4.x, a4.y, a4.z, a4.w};
        float bb[4] = {b4.x, b4.y, b4.z, b4.w};
#pragma unroll
        for (int i = 0; i < 4; i++)
#pragma unroll
            for (int j = 0; j < 4; j++) s[i][j] += a[i] * bb[j];
    }
#pragma unroll
    for (int i = 0; i < 4; i++) {
        int t = ty * 4 + i;
        int ig = (mode == 0) ? (f * 64 + t) : (t * 64 + f);
        float4 o4 = {s[i][0], s[i][1], s[i][2], s[i][3]};
        *(float4*)&outg[head * (NTOK * 64) + ig * 64 + tx * 4] = o4;
    }
}

// ---------------- kernel 4: flash attention, fp16 + ldmatrix + P-in-regs ------
// S C-fragment feeds PV A-fragment directly from registers (m16n8k16 layout
// identity); K/V B-fragments via ldmatrix.x4 (row stride 144B -> 8 row-chunks
// cover all 32 banks, conflict-free). No P smem buffer at all.
#define KH_ST 72  // halves per row (64 + 8 pad)
__global__ __launch_bounds__(128) void attn_kernel() {
    __shared__ __half Ks[64 * KH_ST];  // [key][hd]
    __shared__ __half Vt[64 * KH_ST];  // [hd][key]

    int head = blockIdx.y;
    int q0 = blockIdx.x * 64;
    int tid = threadIdx.x;
    int warp = tid >> 5, lane = tid & 31;
    int g = lane >> 2, tig = lane & 3;
    int r0 = warp * 16 + g, r1 = r0 + 8;

    const __half* qh = g_qh + head * (NTOK * HD) + q0 * HD;
    const __half* kh = g_kh + head * (NTOK * HD);
    const __half* vh = g_vh + head * (HD * NTOK);
    const float* bhg = g_bh + head * (NTOK * 64);
    const float* bwg = g_bw + head * (NTOK * 64);

    // ldmatrix lane addressing: mi = lane>>3 selects matrix, r = lane&7 its row.
    // call (jjp, kk) covers matrices (2jjp,lo),(2jjp,hi),(2jjp+1,lo),(2jjp+1,hi)
    int mi = lane >> 3, lr = lane & 7;
    uint32_t lane_off = ((((mi >> 1) * 8 + lr) * KH_ST) + (mi & 1) * 8) * 2;
    uint32_t kbase = (uint32_t)__cvta_generic_to_shared(Ks) + lane_off;
    uint32_t vbase = (uint32_t)__cvta_generic_to_shared(Vt) + lane_off;

    unsigned qf[4][4];
#pragma unroll
    for (int kk = 0; kk < 4; kk++) {
        qf[kk][0] = *(const unsigned*)&qh[r0 * 64 + kk * 16 + 2 * tig];
        qf[kk][1] = *(const unsigned*)&qh[r1 * 64 + kk * 16 + 2 * tig];
        qf[kk][2] = *(const unsigned*)&qh[r0 * 64 + kk * 16 + 2 * tig + 8];
        qf[kk][3] = *(const unsigned*)&qh[r1 * 64 + kk * 16 + 2 * tig + 8];
    }
    float bw0[16], bw1[16];
#pragma unroll
    for (int jj = 0; jj < 8; jj++) {
        float2 t0 = *(const float2*)&bwg[(q0 + r0) * 64 + jj * 8 + 2 * tig];
        float2 t1 = *(const float2*)&bwg[(q0 + r1) * 64 + jj * 8 + 2 * tig];
        bw0[2 * jj] = t0.x; bw0[2 * jj + 1] = t0.y;
        bw1[2 * jj] = t1.x; bw1[2 * jj + 1] = t1.y;
    }

    float oac[8][4] = {};
    float m0 = -1e30f, m1 = -1e30f, l0 = 0.f, l1 = 0.f;

    for (int kt = 0; kt < 64; kt++) {
        __syncthreads();  // prior K/V fragment reads complete before overwrite
#pragma unroll
        for (int l = 0; l < 512; l += 128) {
            int cc = l + tid;
            int j = cc >> 3, cb = (cc & 7) * 8;
            *(uint4*)&Ks[j * KH_ST + cb] =
                *(const uint4*)&kh[(kt * 64 + j) * 64 + cb];
            *(uint4*)&Vt[j * KH_ST + cb] =
                *(const uint4*)&vh[j * NTOK + kt * 64 + cb];
        }
        __syncthreads();

        // S = (Q/8) . K^T  — B-frags via ldmatrix.x4
        float sac[8][4] = {};
#pragma unroll
        for (int kk = 0; kk < 4; kk++) {
#pragma unroll
            for (int jjp = 0; jjp < 4; jjp++) {
                unsigned b0a, b1a, b0b, b1b;
                ldsm4(b0a, b1a, b0b, b1b,
                      kbase + jjp * (16 * KH_ST * 2) + kk * 32);
                mma16(sac[2 * jjp], qf[kk][0], qf[kk][1], qf[kk][2], qf[kk][3],
                      b0a, b1a);
                mma16(sac[2 * jjp + 1], qf[kk][0], qf[kk][1], qf[kk][2],
                      qf[kk][3], b0b, b1b);
            }
        }

        // biases + online softmax
        float bh0 = __ldg(&bhg[(q0 + r0) * 64 + kt]);
        float bh1 = __ldg(&bhg[(q0 + r1) * 64 + kt]);
        float mt0 = -1e30f, mt1 = -1e30f;
#pragma unroll
        for (int jj = 0; jj < 8; jj++) {
            sac[jj][0] += bh0 + bw0[2 * jj];
            sac[jj][1] += bh0 + bw0[2 * jj + 1];
            sac[jj][2] += bh1 + bw1[2 * jj];
            sac[jj][3] += bh1 + bw1[2 * jj + 1];
            mt0 = fmaxf(mt0, fmaxf(sac[jj][0], sac[jj][1]));
            mt1 = fmaxf(mt1, fmaxf(sac[jj][2], sac[jj][3]));
        }
#pragma unroll
        for (int o = 1; o < 4; o <<= 1) {
            mt0 = fmaxf(mt0, __shfl_xor_sync(0xffffffffu, mt0, o));
            mt1 = fmaxf(mt1, __shfl_xor_sync(0xffffffffu, mt1, o));
        }
        float mn0 = fmaxf(m0, mt0), mn1 = fmaxf(m1, mt1);
        float c0 = __expf(m0 - mn0), c1 = __expf(m1 - mn1);
        float s0 = 0.f, s1 = 0.f;
#pragma unroll
        for (int jj = 0; jj < 8; jj++) {
            sac[jj][0] = __expf(sac[jj][0] - mn0);
            sac[jj][1] = __expf(sac[jj][1] - mn0);
            sac[jj][2] = __expf(sac[jj][2] - mn1);
            sac[jj][3] = __expf(sac[jj][3] - mn1);
            s0 += sac[jj][0] + sac[jj][1];
            s1 += sac[jj][2] + sac[jj][3];
        }
#pragma unroll
        for (int o = 1; o < 4; o <<= 1) {
            s0 += __shfl_xor_sync(0xffffffffu, s0, o);
            s1 += __shfl_xor_sync(0xffffffffu, s1, o);
        }
        l0 = l0 * c0 + s0; l1 = l1 * c1 + s1;
        m0 = mn0; m1 = mn1;
#pragma unroll
        for (int jj = 0; jj < 8; jj++) {
            oac[jj][0] *= c0; oac[jj][1] *= c0;
            oac[jj][2] *= c1; oac[jj][3] *= c1;
        }

        // O += P @ V — P A-frags packed straight from S C-frags (layout identity)
#pragma unroll
        for (int kk = 0; kk < 4; kk++) {
            unsigned a0 = packh2(sac[2 * kk][0], sac[2 * kk][1]);
            unsigned a1 = packh2(sac[2 * kk][2], sac[2 * kk][3]);
            unsigned a2 = packh2(sac[2 * kk + 1][0], sac[2 * kk + 1][1]);
            unsigned a3 = packh2(sac[2 * kk + 1][2], sac[2 * kk + 1][3]);
#pragma unroll
            for (int jjp = 0; jjp < 4; jjp++) {
                unsigned b0a, b1a, b0b, b1b;
                ldsm4(b0a, b1a, b0b, b1b,
                      vbase + jjp * (16 * KH_ST * 2) + kk * 32);
                mma16(oac[2 * jjp], a0, a1, a2, a3, b0a, b1a);
                mma16(oac[2 * jjp + 1], a0, a1, a2, a3, b0b, b1b);
            }
        }
    }

    float inv0 = 1.f / l0, inv1 = 1.f / l1;
#pragma unroll
    for (int jj = 0; jj < 8; jj++) {
        int c = head * 64 + jj * 8 + 2 * tig;
        float2 o0 = {oac[jj][0] * inv0, oac[jj][1] * inv0};
        float2 o1 = {oac[jj][2] * inv1, oac[jj][3] * inv1};
        *(float2*)&g_o[(q0 + r0) * DIM + c] = o0;
        *(float2*)&g_o[(q0 + r1) * DIM + c] = o1;
    }
}

extern "C" void kernel_launch(void* const* d_in, const int* in_sizes, int n_in,
                              void* d_out, int out_size) {
    const float* x      = (const float*)d_in[0];
    const float* W_qkv  = (const float*)d_in[1];
    const float* b_qkv  = (const float*)d_in[2];
    const float* A_q    = (const float*)d_in[3];
    const float* B_q    = (const float*)d_in[4];
    const float* A_v    = (const float*)d_in[5];
    const float* B_v    = (const float*)d_in[6];
    const float* rel_h  = (const float*)d_in[7];
    const float* rel_w  = (const float*)d_in[8];
    const float* W_proj = (const float*)d_in[9];
    const float* b_proj = (const float*)d_in[10];
    float* out = (float*)d_out;

    lora_t_kernel<<<512, 256>>>(x, A_q, A_v);
    qkv_tc_kernel<<<dim3(18, 32), 256>>>(x, W_qkv, b_qkv, B_q, B_v);
    bias2_kernel<<<dim3(64, 12), 256>>>(rel_h, 0);
    bias2_kernel<<<dim3(64, 12), 256>>>(rel_w, 1);
    attn_kernel<<<dim3(64, 12), 128>>>();
    proj_tc_kernel<<<dim3(6, 32), 256>>>(W_proj, b_proj, out);
}